// round 2
// baseline (speedup 1.0000x reference)
#include <cuda_runtime.h>
#include <cstdint>
#include <cstddef>

// ---------------- problem dims ----------------
// B=32, T=10, NOV=3, N=128, F=16, NF=5, EF=2, C=NOV+1=4, SL=2, HID=N*F=2048
// inputs: (B, T*NOV=30, N=128, 3N+NF=389) fp32
#define LEAKY(x) ((x) > 0.0f ? (x) : 0.01f * (x))

constexpr int Bc = 32;
constexpr int Tc = 10;
constexpr int Nc = 128;
constexpr int Fc = 16;
constexpr int Cc = 4;
constexpr int HIDc = 2048;
constexpr int ROWc = 389;      // 3N+NF
constexpr int FLATc = 8192;    // C*N*F

// ---------------- scratch (__device__ globals; no allocs) ----------------
__device__ float g_a1[Bc * Nc * Nc];          // 2 MB: D0^-1/2 A0 D0^-1/2
__device__ float g_a2[Bc * Nc * Nc];          // 2 MB: second normalization
__device__ float g_rs1[Bc * Nc];              // rowsums of a1
__device__ float g_rs2[Bc * Nc];              // rowsums of a2
__device__ float g_ee[Bc * Nc * Fc];          // edge encoder output
__device__ float g_x2[(size_t)Bc * Tc * Cc * Nc * Fc];  // per-(b,t) GCN out, 10.5 MB
__device__ float g_flat[Bc * FLATc];          // graph summed over t
__device__ float g_part[2 * 4 * Bc * HIDc];   // GEMM K-split partials
__device__ float g_hh[2 * Bc * HIDc];         // h (head0) / ha (head1) activated

// ---------------- f32x2 packed-FMA helpers (sm_103a) ----------------
__device__ __forceinline__ unsigned long long f2pk(float x, float y) {
    unsigned long long d;
    asm("mov.b64 %0, {%1, %2};" : "=l"(d) : "f"(x), "f"(y));
    return d;
}
__device__ __forceinline__ void f2un(float& x, float& y, unsigned long long v) {
    asm("mov.b64 {%0, %1}, %2;" : "=f"(x), "=f"(y) : "l"(v));
}
__device__ __forceinline__ unsigned long long fma2(unsigned long long a,
                                                   unsigned long long b,
                                                   unsigned long long c) {
    unsigned long long d;
    asm("fma.rn.f32x2 %0, %1, %2, %3;" : "=l"(d) : "l"(a), "l"(b), "l"(c));
    return d;
}

// ============================================================
// K1: per-batch adjacency normalization + edge encoder
// grid 32, block 256, dynamic smem = 128*129*4
// ============================================================
__global__ void k1_prep(const float* __restrict__ inp,
                        const float* __restrict__ We,
                        const float* __restrict__ be) {
    extern __shared__ float s_a[];       // [128][129]
    __shared__ float s_d[128];
    __shared__ float s_we[32];
    __shared__ float s_be[16];
    const int b = blockIdx.x, tid = threadIdx.x;
    const size_t base = (size_t)b * 30 * 128 * ROWc;

    if (tid < 32) s_we[tid] = We[tid];
    if (tid >= 32 && tid < 48) s_be[tid - 32] = be[tid - 32];
    for (int idx = tid; idx < 128 * 128; idx += 256) {
        int i = idx >> 7, j = idx & 127;
        s_a[i * 129 + j] = inp[base + (size_t)i * ROWc + j];  // raw adj
    }
    __syncthreads();

    // edge_enc[b,j,f] = sum_i leaky(edge[b,i,j,:]@We + be)[f] * adj_raw[i,j]
    if (tid < 128) {
        const int j = tid;
        float acc[16];
#pragma unroll
        for (int f = 0; f < 16; f++) acc[f] = 0.0f;
        for (int i = 0; i < 128; i++) {
            float a = s_a[i * 129 + j];
            const float* ep = inp + base + (size_t)i * ROWc + 128 + 2 * j;
            float e0 = ep[0], e1 = ep[1];
#pragma unroll
            for (int f = 0; f < 16; f++) {
                float v = fmaf(e0, s_we[f], fmaf(e1, s_we[16 + f], s_be[f]));
                v = LEAKY(v);
                acc[f] = fmaf(v, a, acc[f]);
            }
        }
#pragma unroll
        for (int f = 0; f < 16; f++) g_ee[(b * 128 + j) * 16 + f] = acc[f];
    }
    __syncthreads();

    // deg0 from adj with diag=1
    if (tid < 128) {
        const int i = tid;
        float s = 1.0f;  // diagonal forced to 1
        for (int j = 0; j < 128; j++)
            if (j != i) s += s_a[i * 129 + j];
        s_d[i] = 1.0f / sqrtf(fmaxf(s, 1.0f));
    }
    __syncthreads();
    // a1 = d0_i * a0 * d0_j (overwrite smem, write global)
    for (int idx = tid; idx < 128 * 128; idx += 256) {
        int i = idx >> 7, j = idx & 127;
        float a0 = (i == j) ? 1.0f : s_a[i * 129 + j];
        float v = s_d[i] * a0 * s_d[j];
        s_a[i * 129 + j] = v;
        g_a1[b * 16384 + idx] = v;
    }
    __syncthreads();
    if (tid < 128) {
        const int i = tid;
        float s = 0.0f;
        for (int j = 0; j < 128; j++) s += s_a[i * 129 + j];
        g_rs1[b * 128 + i] = s;
        s_d[i] = 1.0f / sqrtf(fmaxf(s, 1.0f));
    }
    __syncthreads();
    // a2 = d1_i * a1 * d1_j
    for (int idx = tid; idx < 128 * 128; idx += 256) {
        int i = idx >> 7, j = idx & 127;
        float v = s_d[i] * s_a[i * 129 + j] * s_d[j];
        s_a[i * 129 + j] = v;
        g_a2[b * 16384 + idx] = v;
    }
    __syncthreads();
    if (tid < 128) {
        const int i = tid;
        float s = 0.0f;
        for (int j = 0; j < 128; j++) s += s_a[i * 129 + j];
        g_rs2[b * 128 + i] = s;
    }
}

// ============================================================
// K2: per-(b,t) GCN (2 layers, factorized)
// grid (32,10), block 256, dynamic smem = 128*129*4
// ============================================================
__global__ void k2_gcn(const float* __restrict__ inp,
                       const float* __restrict__ Wn,
                       const float* __restrict__ bn,
                       const float* __restrict__ Wg,
                       const float* __restrict__ bgl,
                       const float* __restrict__ gb) {
    extern __shared__ float s_a[];       // [128][129]
    __shared__ float s_xs[2048];
    __shared__ float s_z[2048];
    __shared__ float s_wg[2048];         // Wg[2][4][16][16]
    __shared__ float s_bgl[128];         // bgl[2][4][16]
    __shared__ float s_gb[64];           // gbias[4][16]
    __shared__ float s_wn[80];           // Wn[5][16]
    __shared__ float s_bn[16];
    __shared__ float s_rs[256];          // rs1[128] | rs2[128]

    const int b = blockIdx.x, t = blockIdx.y, tid = threadIdx.x;
    for (int i = tid; i < 2048; i += 256) s_wg[i] = Wg[i];
    if (tid < 128) s_bgl[tid] = bgl[tid];
    if (tid < 64) s_gb[tid] = gb[tid];
    if (tid < 80) s_wn[tid] = Wn[tid];
    if (tid < 16) s_bn[tid] = bn[tid];
    if (tid < 128) s_rs[tid] = g_rs1[b * 128 + tid];
    else           s_rs[tid] = g_rs2[b * 128 + tid - 128];
    for (int idx = tid; idx < 16384; idx += 256) {
        int i = idx >> 7, j = idx & 127;
        s_a[i * 129 + j] = g_a1[b * 16384 + idx];
    }
    __syncthreads();

    const int n = tid & 127;
    const int f0 = (tid >> 7) * 8;

    // xs[n,f] = edge_enc[b,n,f] + sum_v leaky(node@Wn + bn)
    {
        float acc[8];
        const float* ee = &g_ee[(b * 128 + n) * 16 + f0];
#pragma unroll
        for (int f = 0; f < 8; f++) acc[f] = ee[f];
#pragma unroll
        for (int v = 0; v < 3; v++) {
            const float* np =
                inp + ((size_t)(b * 30 + t * 3 + v) * 128 + n) * ROWc + 384;
            float nk0 = np[0], nk1 = np[1], nk2 = np[2], nk3 = np[3], nk4 = np[4];
#pragma unroll
            for (int f = 0; f < 8; f++) {
                int fc = f0 + f;
                float s = s_bn[fc];
                s = fmaf(nk0, s_wn[0 * 16 + fc], s);
                s = fmaf(nk1, s_wn[1 * 16 + fc], s);
                s = fmaf(nk2, s_wn[2 * 16 + fc], s);
                s = fmaf(nk3, s_wn[3 * 16 + fc], s);
                s = fmaf(nk4, s_wn[4 * 16 + fc], s);
                acc[f] += LEAKY(s);
            }
        }
#pragma unroll
        for (int f = 0; f < 8; f++) s_xs[n * 16 + f0 + f] = acc[f];
    }
    __syncthreads();

    // z1 = a1 @ xs
    {
        float acc[8] = {};
#pragma unroll 4
        for (int m = 0; m < 128; m++) {
            float a = s_a[n * 129 + m];
            float4 x0 = *(const float4*)&s_xs[m * 16 + f0];
            float4 x1 = *(const float4*)&s_xs[m * 16 + f0 + 4];
            acc[0] = fmaf(a, x0.x, acc[0]); acc[1] = fmaf(a, x0.y, acc[1]);
            acc[2] = fmaf(a, x0.z, acc[2]); acc[3] = fmaf(a, x0.w, acc[3]);
            acc[4] = fmaf(a, x1.x, acc[4]); acc[5] = fmaf(a, x1.y, acc[5]);
            acc[6] = fmaf(a, x1.z, acc[6]); acc[7] = fmaf(a, x1.w, acc[7]);
        }
#pragma unroll
        for (int f = 0; f < 8; f++) s_z[n * 16 + f0 + f] = acc[f];
    }
    __syncthreads();

    // layer-1 channel mix:  xs2[n,o] = sum_c leaky(z1@Wg0[c] + rs1*4*bgl0[c] + gb[c])
    {
        float zr[16];
#pragma unroll
        for (int f = 0; f < 16; f++) zr[f] = s_z[n * 16 + f];
        float rs4 = 4.0f * s_rs[n];
        float outv[8];
#pragma unroll
        for (int o = 0; o < 8; o++) {
            int oc = f0 + o;
            float sum = 0.0f;
#pragma unroll
            for (int c = 0; c < 4; c++) {
                float u = fmaf(rs4, s_bgl[c * 16 + oc], s_gb[c * 16 + oc]);
#pragma unroll
                for (int f = 0; f < 16; f++)
                    u = fmaf(zr[f], s_wg[(c * 16 + f) * 16 + oc], u);
                sum += LEAKY(u);
            }
            outv[o] = sum;
        }
#pragma unroll
        for (int o = 0; o < 8; o++) s_xs[n * 16 + f0 + o] = outv[o];
    }
    __syncthreads();

    // swap in a2
    for (int idx = tid; idx < 16384; idx += 256) {
        int i = idx >> 7, j = idx & 127;
        s_a[i * 129 + j] = g_a2[b * 16384 + idx];
    }
    __syncthreads();

    // z2 = a2 @ xs2
    {
        float acc[8] = {};
#pragma unroll 4
        for (int m = 0; m < 128; m++) {
            float a = s_a[n * 129 + m];
            float4 x0 = *(const float4*)&s_xs[m * 16 + f0];
            float4 x1 = *(const float4*)&s_xs[m * 16 + f0 + 4];
            acc[0] = fmaf(a, x0.x, acc[0]); acc[1] = fmaf(a, x0.y, acc[1]);
            acc[2] = fmaf(a, x0.z, acc[2]); acc[3] = fmaf(a, x0.w, acc[3]);
            acc[4] = fmaf(a, x1.x, acc[4]); acc[5] = fmaf(a, x1.y, acc[5]);
            acc[6] = fmaf(a, x1.z, acc[6]); acc[7] = fmaf(a, x1.w, acc[7]);
        }
#pragma unroll
        for (int f = 0; f < 8; f++) s_z[n * 16 + f0 + f] = acc[f];
    }
    __syncthreads();

    // layer-2 channel mix -> write all 4 channels to global scratch
    {
        float zr[16];
#pragma unroll
        for (int f = 0; f < 16; f++) zr[f] = s_z[n * 16 + f];
        float rs4 = 4.0f * s_rs[128 + n];
        size_t obase = ((size_t)(b * 10 + t) * 4) * 2048 + n * 16 + f0;
#pragma unroll
        for (int o = 0; o < 8; o++) {
            int oc = f0 + o;
#pragma unroll
            for (int c = 0; c < 4; c++) {
                float u = fmaf(rs4, s_bgl[64 + c * 16 + oc], s_gb[c * 16 + oc]);
#pragma unroll
                for (int f = 0; f < 16; f++)
                    u = fmaf(zr[f], s_wg[1024 + (c * 16 + f) * 16 + oc], u);
                g_x2[obase + c * 2048 + o] = LEAKY(u);
            }
        }
    }
}

// ============================================================
// K3: reduce over t -> flat (deterministic order)
// ============================================================
__global__ void k3_reduce() {
    int idx = blockIdx.x * 256 + threadIdx.x;  // 262144 total
    int b = idx >> 13;
    int j = idx & 8191;
    const float* p = &g_x2[(size_t)b * 10 * 8192 + j];
    float s = 0.0f;
#pragma unroll
    for (int t = 0; t < 10; t++) s += p[(size_t)t * 8192];
    g_flat[idx] = s;
}

// ============================================================
// K4: flat(32x8192) @ W(8192x2048), K-split x4, f32x2 packed FMA
// grid (16 col-tiles, 4 k-chunks, 2 heads), block 256
// ============================================================
__global__ void k4_gemm(const float* __restrict__ Wc1,
                        const float* __restrict__ Wa1) {
    __shared__ float s_f[32 * 64];
    const int tid = threadIdx.x;
    const int head = blockIdx.z;
    const float* __restrict__ W = head ? Wa1 : Wc1;
    const int col = blockIdx.x * 128 + (tid & 31) * 4;
    const int row0 = (tid >> 5) * 4;
    const int kbase = blockIdx.y * 2048;

    unsigned long long acc[4][2];
#pragma unroll
    for (int q = 0; q < 4; q++) { acc[q][0] = 0ULL; acc[q][1] = 0ULL; }

    for (int k0 = kbase; k0 < kbase + 2048; k0 += 64) {
#pragma unroll
        for (int i = 0; i < 8; i++) {
            int idx = tid + i * 256;
            int r = idx >> 6, kk = idx & 63;
            s_f[idx] = g_flat[r * 8192 + k0 + kk];
        }
        __syncthreads();
#pragma unroll 8
        for (int kk = 0; kk < 64; kk++) {
            const ulonglong2 w =
                *(const ulonglong2*)&W[(size_t)(k0 + kk) * 2048 + col];
#pragma unroll
            for (int q = 0; q < 4; q++) {
                float fr = s_f[(row0 + q) * 64 + kk];
                unsigned long long fr2 = f2pk(fr, fr);
                acc[q][0] = fma2(fr2, w.x, acc[q][0]);
                acc[q][1] = fma2(fr2, w.y, acc[q][1]);
            }
        }
        __syncthreads();
    }

    size_t base = (size_t)(head * 4 + blockIdx.y) * 32 * 2048;
#pragma unroll
    for (int q = 0; q < 4; q++) {
        float a0, a1v, a2v, a3v;
        f2un(a0, a1v, acc[q][0]);
        f2un(a2v, a3v, acc[q][1]);
        float* p = &g_part[base + (size_t)(row0 + q) * 2048 + col];
        p[0] = a0; p[1] = a1v; p[2] = a2v; p[3] = a3v;
    }
}

// ============================================================
// K5a: reduce K-chunk partials + bias + leaky
// ============================================================
__global__ void k5a_act(const float* __restrict__ bc1,
                        const float* __restrict__ ba1) {
    const int head = blockIdx.y;
    const int i = blockIdx.x * 256 + threadIdx.x;  // 0..65535
    const int colv = i & 2047;
    size_t hb = (size_t)head * 4 * 65536;
    float s = (head ? ba1 : bc1)[colv];
    s += g_part[hb + i] + g_part[hb + 65536 + i] + g_part[hb + 2 * 65536 + i] +
         g_part[hb + 3 * 65536 + i];
    g_hh[head * 65536 + i] = LEAKY(s);
}

// ============================================================
// K5b: small heads -> critic (32) | actor (32x16)
// grid 32, block 256
// ============================================================
__global__ void k5b_heads(const float* __restrict__ Wc2,
                          const float* __restrict__ bc2,
                          const float* __restrict__ Wc3,
                          const float* __restrict__ bc3,
                          const float* __restrict__ Wa2,
                          const float* __restrict__ ba2,
                          float* __restrict__ out) {
    __shared__ float s_h[2048];
    __shared__ float s_ha[2048];
    __shared__ float s_r[32];
    const int b = blockIdx.x, tid = threadIdx.x;
    for (int i = tid; i < 2048; i += 256) {
        s_h[i] = g_hh[b * 2048 + i];
        s_ha[i] = g_hh[65536 + b * 2048 + i];
    }
    __syncthreads();
    const int w = tid >> 5, lane = tid & 31;
    for (int d = w; d < 32; d += 8) {
        const bool is_act = d >= 16;
        const int f = d & 15;
        const float* src = is_act ? s_ha : s_h;
        const float* Wp = is_act ? Wa2 : Wc2;
        float s = 0.0f;
        for (int k = lane; k < 2048; k += 32) s = fmaf(src[k], Wp[k * 16 + f], s);
#pragma unroll
        for (int off = 16; off; off >>= 1) s += __shfl_down_sync(0xffffffffu, s, off);
        if (lane == 0) {
            float v = s + (is_act ? ba2[f] : bc2[f]);
            s_r[d] = LEAKY(v);
        }
    }
    __syncthreads();
    if (tid == 0) {
        float cr = bc3[0];
#pragma unroll
        for (int f = 0; f < 16; f++) cr = fmaf(s_r[f], Wc3[f], cr);
        out[b] = cr;
    }
    if (tid < 16) out[32 + b * 16 + tid] = s_r[16 + tid];
}

// ============================================================
extern "C" void kernel_launch(void* const* d_in, const int* in_sizes, int n_in,
                              void* d_out, int out_size) {
    (void)in_sizes; (void)n_in; (void)out_size;
    const float* inp = (const float*)d_in[0];
    const float* We  = (const float*)d_in[1];
    const float* be  = (const float*)d_in[2];
    const float* Wn  = (const float*)d_in[3];
    const float* bn  = (const float*)d_in[4];
    const float* Wg  = (const float*)d_in[5];
    const float* bgl = (const float*)d_in[6];
    const float* gb  = (const float*)d_in[7];
    const float* Wc1 = (const float*)d_in[8];
    const float* bc1 = (const float*)d_in[9];
    const float* Wc2 = (const float*)d_in[10];
    const float* bc2 = (const float*)d_in[11];
    const float* Wc3 = (const float*)d_in[12];
    const float* bc3 = (const float*)d_in[13];
    const float* Wa1 = (const float*)d_in[14];
    const float* ba1 = (const float*)d_in[15];
    const float* Wa2 = (const float*)d_in[16];
    const float* ba2 = (const float*)d_in[17];

    const int dyn = 128 * 129 * 4;  // 66048 B
    cudaFuncSetAttribute(k1_prep, cudaFuncAttributeMaxDynamicSharedMemorySize, dyn);
    cudaFuncSetAttribute(k2_gcn, cudaFuncAttributeMaxDynamicSharedMemorySize, dyn);

    k1_prep<<<32, 256, dyn>>>(inp, We, be);
    k2_gcn<<<dim3(32, 10), 256, dyn>>>(inp, Wn, bn, Wg, bgl, gb);
    k3_reduce<<<1024, 256>>>();
    k4_gemm<<<dim3(16, 4, 2), 256>>>(Wc1, Wa1);
    k5a_act<<<dim3(256, 2), 256>>>(bc1, ba1);
    k5b_heads<<<32, 256>>>(Wc2, bc2, Wc3, bc3, Wa2, ba2, (float*)d_out);
}

// round 3
// speedup vs baseline: 2.2776x; 2.2776x over previous
#include <cuda_runtime.h>
#include <cstdint>
#include <cstddef>

// ---------------- problem dims ----------------
// B=32, T=10, NOV=3, N=128, F=16, NF=5, EF=2, C=4, SL=2, HID=2048
#define LEAKY(x) ((x) > 0.0f ? (x) : 0.01f * (x))

constexpr int Bc = 32;
constexpr int Nc = 128;
constexpr int Fc = 16;
constexpr int HIDc = 2048;
constexpr int ROWc = 389;      // 3N+NF
constexpr int FLATc = 8192;    // C*N*F
constexpr int KSPLIT = 32;     // k4 K-split factor

// ---------------- scratch (__device__ globals; no allocs) ----------------
__device__ float g_a1[Bc * Nc * Nc];
__device__ float g_a2[Bc * Nc * Nc];
__device__ float g_rs1[Bc * Nc];
__device__ float g_rs2[Bc * Nc];
__device__ float g_ee[Bc * Nc * Fc];
__device__ float g_x2[(size_t)Bc * 10 * 4 * Nc * Fc];   // per-(b,t) GCN out
__device__ float g_flat[Bc * FLATc];
__device__ float g_part2[(size_t)2 * KSPLIT * Bc * HIDc];  // 16 MB partials
__device__ float g_hh[2 * Bc * HIDc];

// ---------------- f32x2 packed-FMA helpers (sm_103a) ----------------
__device__ __forceinline__ void f2un(float& x, float& y, unsigned long long v) {
    asm("mov.b64 {%0, %1}, %2;" : "=f"(x), "=f"(y) : "l"(v));
}
__device__ __forceinline__ unsigned long long fma2(unsigned long long a,
                                                   unsigned long long b,
                                                   unsigned long long c) {
    unsigned long long d;
    asm("fma.rn.f32x2 %0, %1, %2, %3;" : "=l"(d) : "l"(a), "l"(b), "l"(c));
    return d;
}

// ============================================================
// K1: per-batch adjacency normalization + edge encoder
// grid 32, block 256, dynamic smem = 128*129*4
// ============================================================
__global__ void k1_prep(const float* __restrict__ inp,
                        const float* __restrict__ We,
                        const float* __restrict__ be) {
    extern __shared__ float s_a[];       // [128][129]
    __shared__ float s_d[128];
    __shared__ float s_we[32];
    __shared__ float s_be[16];
    __shared__ float s_part[2048];       // half-sum buffer for edge enc
    const int b = blockIdx.x, tid = threadIdx.x;
    const size_t base = (size_t)b * 30 * 128 * ROWc;

    if (tid < 32) s_we[tid] = We[tid];
    if (tid >= 32 && tid < 48) s_be[tid - 32] = be[tid - 32];
    for (int idx = tid; idx < 128 * 128; idx += 256) {
        int i = idx >> 7, j = idx & 127;
        s_a[i * 129 + j] = inp[base + (size_t)i * ROWc + j];  // raw adj
    }
    __syncthreads();

    // edge_enc[b,j,f] = sum_i leaky(edge[b,i,j,:]@We + be)[f] * adj_raw[i,j]
    // split i-range over two halves of the block
    {
        const int j = tid & 127;
        const int half = tid >> 7;
        float acc[16];
#pragma unroll
        for (int f = 0; f < 16; f++) acc[f] = 0.0f;
        for (int i = half * 64; i < half * 64 + 64; i++) {
            float a = s_a[i * 129 + j];
            const float* ep = inp + base + (size_t)i * ROWc + 128 + 2 * j;
            float e0 = ep[0], e1 = ep[1];
#pragma unroll
            for (int f = 0; f < 16; f++) {
                float v = fmaf(e0, s_we[f], fmaf(e1, s_we[16 + f], s_be[f]));
                v = LEAKY(v);
                acc[f] = fmaf(v, a, acc[f]);
            }
        }
        if (half == 1) {
#pragma unroll
            for (int f = 0; f < 16; f++) s_part[j * 16 + f] = acc[f];
        }
        __syncthreads();
        if (half == 0) {
#pragma unroll
            for (int f = 0; f < 16; f++)
                g_ee[(b * 128 + j) * 16 + f] = acc[f] + s_part[j * 16 + f];
        }
    }
    __syncthreads();

    // deg0 from adj with diag=1
    if (tid < 128) {
        const int i = tid;
        float s = 1.0f;
        for (int j = 0; j < 128; j++)
            if (j != i) s += s_a[i * 129 + j];
        s_d[i] = 1.0f / sqrtf(fmaxf(s, 1.0f));
    }
    __syncthreads();
    for (int idx = tid; idx < 128 * 128; idx += 256) {
        int i = idx >> 7, j = idx & 127;
        float a0 = (i == j) ? 1.0f : s_a[i * 129 + j];
        float v = s_d[i] * a0 * s_d[j];
        s_a[i * 129 + j] = v;
        g_a1[b * 16384 + idx] = v;
    }
    __syncthreads();
    if (tid < 128) {
        const int i = tid;
        float s = 0.0f;
        for (int j = 0; j < 128; j++) s += s_a[i * 129 + j];
        g_rs1[b * 128 + i] = s;
        s_d[i] = 1.0f / sqrtf(fmaxf(s, 1.0f));
    }
    __syncthreads();
    for (int idx = tid; idx < 128 * 128; idx += 256) {
        int i = idx >> 7, j = idx & 127;
        float v = s_d[i] * s_a[i * 129 + j] * s_d[j];
        s_a[i * 129 + j] = v;
        g_a2[b * 16384 + idx] = v;
    }
    __syncthreads();
    if (tid < 128) {
        const int i = tid;
        float s = 0.0f;
        for (int j = 0; j < 128; j++) s += s_a[i * 129 + j];
        g_rs2[b * 128 + i] = s;
    }
}

// ============================================================
// K2: per-(b,t) GCN (2 layers, factorized over channels)
// grid (32,10), block 256, dynamic smem = 128*129*4
// ============================================================
__global__ void k2_gcn(const float* __restrict__ inp,
                       const float* __restrict__ Wn,
                       const float* __restrict__ bn,
                       const float* __restrict__ Wg,
                       const float* __restrict__ bgl,
                       const float* __restrict__ gb) {
    extern __shared__ float s_a[];       // [128][129]
    __shared__ float s_xs[2048];
    __shared__ float s_z[2048];
    __shared__ float s_wg[2048];
    __shared__ float s_bgl[128];
    __shared__ float s_gb[64];
    __shared__ float s_wn[80];
    __shared__ float s_bn[16];
    __shared__ float s_rs[256];

    const int b = blockIdx.x, t = blockIdx.y, tid = threadIdx.x;
    for (int i = tid; i < 2048; i += 256) s_wg[i] = Wg[i];
    if (tid < 128) s_bgl[tid] = bgl[tid];
    if (tid < 64) s_gb[tid] = gb[tid];
    if (tid < 80) s_wn[tid] = Wn[tid];
    if (tid < 16) s_bn[tid] = bn[tid];
    if (tid < 128) s_rs[tid] = g_rs1[b * 128 + tid];
    else           s_rs[tid] = g_rs2[b * 128 + tid - 128];
    for (int idx = tid; idx < 16384; idx += 256) {
        int i = idx >> 7, j = idx & 127;
        s_a[i * 129 + j] = g_a1[b * 16384 + idx];
    }
    __syncthreads();

    const int n = tid & 127;
    const int f0 = (tid >> 7) * 8;

    // xs[n,f] = edge_enc + sum_v leaky(node@Wn + bn)
    {
        float acc[8];
        const float* ee = &g_ee[(b * 128 + n) * 16 + f0];
#pragma unroll
        for (int f = 0; f < 8; f++) acc[f] = ee[f];
#pragma unroll
        for (int v = 0; v < 3; v++) {
            const float* np =
                inp + ((size_t)(b * 30 + t * 3 + v) * 128 + n) * ROWc + 384;
            float nk0 = np[0], nk1 = np[1], nk2 = np[2], nk3 = np[3], nk4 = np[4];
#pragma unroll
            for (int f = 0; f < 8; f++) {
                int fc = f0 + f;
                float s = s_bn[fc];
                s = fmaf(nk0, s_wn[fc], s);
                s = fmaf(nk1, s_wn[16 + fc], s);
                s = fmaf(nk2, s_wn[32 + fc], s);
                s = fmaf(nk3, s_wn[48 + fc], s);
                s = fmaf(nk4, s_wn[64 + fc], s);
                acc[f] += LEAKY(s);
            }
        }
#pragma unroll
        for (int f = 0; f < 8; f++) s_xs[n * 16 + f0 + f] = acc[f];
    }
    __syncthreads();

    // z1 = a1 @ xs
    {
        float acc[8] = {};
#pragma unroll 4
        for (int m = 0; m < 128; m++) {
            float a = s_a[n * 129 + m];
            float4 x0 = *(const float4*)&s_xs[m * 16 + f0];
            float4 x1 = *(const float4*)&s_xs[m * 16 + f0 + 4];
            acc[0] = fmaf(a, x0.x, acc[0]); acc[1] = fmaf(a, x0.y, acc[1]);
            acc[2] = fmaf(a, x0.z, acc[2]); acc[3] = fmaf(a, x0.w, acc[3]);
            acc[4] = fmaf(a, x1.x, acc[4]); acc[5] = fmaf(a, x1.y, acc[5]);
            acc[6] = fmaf(a, x1.z, acc[6]); acc[7] = fmaf(a, x1.w, acc[7]);
        }
#pragma unroll
        for (int f = 0; f < 8; f++) s_z[n * 16 + f0 + f] = acc[f];
    }
    __syncthreads();

    // layer-1 channel mix
    {
        float zr[16];
#pragma unroll
        for (int f = 0; f < 16; f++) zr[f] = s_z[n * 16 + f];
        float rs4 = 4.0f * s_rs[n];
        float outv[8];
#pragma unroll
        for (int o = 0; o < 8; o++) {
            int oc = f0 + o;
            float sum = 0.0f;
#pragma unroll
            for (int c = 0; c < 4; c++) {
                float u = fmaf(rs4, s_bgl[c * 16 + oc], s_gb[c * 16 + oc]);
#pragma unroll
                for (int f = 0; f < 16; f++)
                    u = fmaf(zr[f], s_wg[(c * 16 + f) * 16 + oc], u);
                sum += LEAKY(u);
            }
            outv[o] = sum;
        }
#pragma unroll
        for (int o = 0; o < 8; o++) s_xs[n * 16 + f0 + o] = outv[o];
    }
    __syncthreads();

    for (int idx = tid; idx < 16384; idx += 256) {
        int i = idx >> 7, j = idx & 127;
        s_a[i * 129 + j] = g_a2[b * 16384 + idx];
    }
    __syncthreads();

    // z2 = a2 @ xs2
    {
        float acc[8] = {};
#pragma unroll 4
        for (int m = 0; m < 128; m++) {
            float a = s_a[n * 129 + m];
            float4 x0 = *(const float4*)&s_xs[m * 16 + f0];
            float4 x1 = *(const float4*)&s_xs[m * 16 + f0 + 4];
            acc[0] = fmaf(a, x0.x, acc[0]); acc[1] = fmaf(a, x0.y, acc[1]);
            acc[2] = fmaf(a, x0.z, acc[2]); acc[3] = fmaf(a, x0.w, acc[3]);
            acc[4] = fmaf(a, x1.x, acc[4]); acc[5] = fmaf(a, x1.y, acc[5]);
            acc[6] = fmaf(a, x1.z, acc[6]); acc[7] = fmaf(a, x1.w, acc[7]);
        }
#pragma unroll
        for (int f = 0; f < 8; f++) s_z[n * 16 + f0 + f] = acc[f];
    }
    __syncthreads();

    // layer-2 channel mix -> global scratch
    {
        float zr[16];
#pragma unroll
        for (int f = 0; f < 16; f++) zr[f] = s_z[n * 16 + f];
        float rs4 = 4.0f * s_rs[128 + n];
        size_t obase = ((size_t)(b * 10 + t) * 4) * 2048 + n * 16 + f0;
#pragma unroll
        for (int o = 0; o < 8; o++) {
            int oc = f0 + o;
#pragma unroll
            for (int c = 0; c < 4; c++) {
                float u = fmaf(rs4, s_bgl[64 + c * 16 + oc], s_gb[c * 16 + oc]);
#pragma unroll
                for (int f = 0; f < 16; f++)
                    u = fmaf(zr[f], s_wg[1024 + (c * 16 + f) * 16 + oc], u);
                g_x2[obase + c * 2048 + o] = LEAKY(u);
            }
        }
    }
}

// ============================================================
// K3: reduce over t -> flat
// ============================================================
__global__ void k3_reduce() {
    int idx = blockIdx.x * 256 + threadIdx.x;
    int b = idx >> 13;
    int j = idx & 8191;
    const float* p = &g_x2[(size_t)b * 10 * 8192 + j];
    float s = 0.0f;
#pragma unroll
    for (int t = 0; t < 10; t++) s += p[(size_t)t * 8192];
    g_flat[idx] = s;
}

// ============================================================
// K4: flat(32x8192) @ W(8192x2048), heads x2.
// Register-resident 32-row accumulators (f32x2), W loaded ONCE.
// grid (8 coltiles x 32 ksplits x 2 heads) = 512 CTAs, block 64.
// ============================================================
__global__ void __launch_bounds__(64, 4)
k4_gemm(const float* __restrict__ Wc1, const float* __restrict__ Wa1) {
    __shared__ float4 s_fd[16 * 32];   // [k-pair][row]: (v,v,v',v') duplicated flat
    const int tid = threadIdx.x;
    const int head = blockIdx.z;
    const float* __restrict__ W = head ? Wa1 : Wc1;
    const int col = blockIdx.x * 256 + tid * 4;
    const int kbase = blockIdx.y * 256;   // 8192 / 32

    unsigned long long acc[32][2];
#pragma unroll
    for (int r = 0; r < 32; r++) { acc[r][0] = 0ULL; acc[r][1] = 0ULL; }

    for (int stage = 0; stage < 8; stage++) {
        const int k0 = kbase + stage * 32;
        __syncthreads();
        for (int idx = tid; idx < 1024; idx += 64) {
            int kk = idx & 31, r = idx >> 5;
            float v = g_flat[r * 8192 + k0 + kk];
            float2* dst = (float2*)&s_fd[(kk >> 1) * 32 + r];
            dst[kk & 1] = make_float2(v, v);
        }
        __syncthreads();
#pragma unroll 4
        for (int kp = 0; kp < 16; kp++) {
            const int k = k0 + kp * 2;
            const ulonglong2 w0 = *(const ulonglong2*)&W[(size_t)k * 2048 + col];
            const ulonglong2 w1 =
                *(const ulonglong2*)&W[(size_t)(k + 1) * 2048 + col];
            const ulonglong2* fd = (const ulonglong2*)&s_fd[kp * 32];
#pragma unroll
            for (int r = 0; r < 32; r++) {
                ulonglong2 d = fd[r];
                acc[r][0] = fma2(d.x, w0.x, acc[r][0]);
                acc[r][1] = fma2(d.x, w0.y, acc[r][1]);
                acc[r][0] = fma2(d.y, w1.x, acc[r][0]);
                acc[r][1] = fma2(d.y, w1.y, acc[r][1]);
            }
        }
    }

    const size_t base = ((size_t)(head * KSPLIT + blockIdx.y)) * 65536;
#pragma unroll
    for (int r = 0; r < 32; r++) {
        float4 o;
        f2un(o.x, o.y, acc[r][0]);
        f2un(o.z, o.w, acc[r][1]);
        *(float4*)&g_part2[base + (size_t)r * 2048 + col] = o;
    }
}

// ============================================================
// K5a: reduce K-split partials + bias + leaky
// ============================================================
__global__ void k5a_act(const float* __restrict__ bc1,
                        const float* __restrict__ ba1) {
    const int head = blockIdx.y;
    const int i = blockIdx.x * 256 + threadIdx.x;  // 0..65535
    float s = (head ? ba1 : bc1)[i & 2047];
    const size_t hb = (size_t)head * KSPLIT * 65536;
#pragma unroll
    for (int p = 0; p < KSPLIT; p++) s += g_part2[hb + (size_t)p * 65536 + i];
    g_hh[head * 65536 + i] = LEAKY(s);
}

// ============================================================
// K5b: small heads (W2 staged via smem) -> critic | actor
// grid 32, block 256
// ============================================================
__global__ void k5b_heads(const float* __restrict__ Wc2,
                          const float* __restrict__ bc2,
                          const float* __restrict__ Wc3,
                          const float* __restrict__ bc3,
                          const float* __restrict__ Wa2,
                          const float* __restrict__ ba2,
                          float* __restrict__ out) {
    __shared__ float s_h[2048];
    __shared__ float s_ha[2048];
    __shared__ float s_w[256 * 17];   // pitch-17: conflict-free
    __shared__ float s_r[32];
    const int b = blockIdx.x, tid = threadIdx.x;
    for (int i = tid; i < 2048; i += 256) {
        s_h[i] = g_hh[b * 2048 + i];
        s_ha[i] = g_hh[65536 + b * 2048 + i];
    }
    const int w = tid >> 5, lane = tid & 31;
    float psc[2] = {0.0f, 0.0f}, psa[2] = {0.0f, 0.0f};

    for (int c = 0; c < 8; c++) {
        // --- critic W2 chunk ---
        __syncthreads();
        for (int idx = tid; idx < 4096; idx += 256) {
            int k = idx >> 4, f = idx & 15;
            s_w[k * 17 + f] = Wc2[c * 4096 + idx];
        }
        __syncthreads();
#pragma unroll
        for (int dd = 0; dd < 2; dd++) {
            const int f = w + dd * 8;
            float s = 0.0f;
#pragma unroll
            for (int ki = 0; ki < 8; ki++) {
                int k = ki * 32 + lane;
                s = fmaf(s_h[c * 256 + k], s_w[k * 17 + f], s);
            }
            psc[dd] += s;
        }
        // --- actor W2 chunk ---
        __syncthreads();
        for (int idx = tid; idx < 4096; idx += 256) {
            int k = idx >> 4, f = idx & 15;
            s_w[k * 17 + f] = Wa2[c * 4096 + idx];
        }
        __syncthreads();
#pragma unroll
        for (int dd = 0; dd < 2; dd++) {
            const int f = w + dd * 8;
            float s = 0.0f;
#pragma unroll
            for (int ki = 0; ki < 8; ki++) {
                int k = ki * 32 + lane;
                s = fmaf(s_ha[c * 256 + k], s_w[k * 17 + f], s);
            }
            psa[dd] += s;
        }
    }
#pragma unroll
    for (int dd = 0; dd < 2; dd++) {
        float sc = psc[dd], sa = psa[dd];
#pragma unroll
        for (int off = 16; off; off >>= 1) {
            sc += __shfl_down_sync(0xffffffffu, sc, off);
            sa += __shfl_down_sync(0xffffffffu, sa, off);
        }
        if (lane == 0) {
            int f = w + dd * 8;
            float vc = sc + bc2[f];
            float va = sa + ba2[f];
            s_r[f] = LEAKY(vc);
            s_r[16 + f] = LEAKY(va);
        }
    }
    __syncthreads();
    if (tid == 0) {
        float cr = bc3[0];
#pragma unroll
        for (int f = 0; f < 16; f++) cr = fmaf(s_r[f], Wc3[f], cr);
        out[b] = cr;
    }
    if (tid < 16) out[32 + b * 16 + tid] = s_r[16 + tid];
}

// ============================================================
extern "C" void kernel_launch(void* const* d_in, const int* in_sizes, int n_in,
                              void* d_out, int out_size) {
    (void)in_sizes; (void)n_in; (void)out_size;
    const float* inp = (const float*)d_in[0];
    const float* We  = (const float*)d_in[1];
    const float* be  = (const float*)d_in[2];
    const float* Wn  = (const float*)d_in[3];
    const float* bn  = (const float*)d_in[4];
    const float* Wg  = (const float*)d_in[5];
    const float* bgl = (const float*)d_in[6];
    const float* gb  = (const float*)d_in[7];
    const float* Wc1 = (const float*)d_in[8];
    const float* bc1 = (const float*)d_in[9];
    const float* Wc2 = (const float*)d_in[10];
    const float* bc2 = (const float*)d_in[11];
    const float* Wc3 = (const float*)d_in[12];
    const float* bc3 = (const float*)d_in[13];
    const float* Wa1 = (const float*)d_in[14];
    const float* ba1 = (const float*)d_in[15];
    const float* Wa2 = (const float*)d_in[16];
    const float* ba2 = (const float*)d_in[17];

    const int dyn = 128 * 129 * 4;  // 66048 B
    cudaFuncSetAttribute(k1_prep, cudaFuncAttributeMaxDynamicSharedMemorySize, dyn);
    cudaFuncSetAttribute(k2_gcn, cudaFuncAttributeMaxDynamicSharedMemorySize, dyn);

    k1_prep<<<32, 256, dyn>>>(inp, We, be);
    k2_gcn<<<dim3(32, 10), 256, dyn>>>(inp, Wn, bn, Wg, bgl, gb);
    k3_reduce<<<1024, 256>>>();
    k4_gemm<<<dim3(8, KSPLIT, 2), 64>>>(Wc1, Wa1);
    k5a_act<<<dim3(256, 2), 256>>>(bc1, ba1);
    k5b_heads<<<32, 256>>>(Wc2, bc2, Wc3, bc3, Wa2, ba2, (float*)d_out);
}

// round 4
// speedup vs baseline: 2.6389x; 1.1586x over previous
#include <cuda_runtime.h>
#include <cstdint>
#include <cstddef>

// ---------------- problem dims ----------------
// B=32, T=10, NOV=3, N=128, F=16, NF=5, EF=2, C=4, SL=2, HID=2048
#define LEAKY(x) ((x) > 0.0f ? (x) : 0.01f * (x))

constexpr int Bc = 32;
constexpr int Nc = 128;
constexpr int HIDc = 2048;
constexpr int ROWc = 389;      // 3N+NF
constexpr int FLATc = 8192;    // C*N*F
constexpr int KSPLIT = 32;     // k4 K-split factor

// ---------------- scratch (__device__ globals; no allocs) ----------------
__device__ float g_a1[Bc * Nc * Nc];
__device__ float g_a2[Bc * Nc * Nc];
__device__ float g_rs1[Bc * Nc];
__device__ float g_rs2[Bc * Nc];
__device__ float g_ee[Bc * Nc * 16];
__device__ float g_x2[(size_t)Bc * 10 * 4 * Nc * 16];
__device__ float g_flat[Bc * FLATc];
__device__ float g_part2[(size_t)2 * KSPLIT * Bc * HIDc];
__device__ float g_hh[2 * Bc * HIDc];

// ---------------- f32x2 packed-FMA helpers (sm_103a) ----------------
__device__ __forceinline__ unsigned long long f2pk(float x, float y) {
    unsigned long long d;
    asm("mov.b64 %0, {%1, %2};" : "=l"(d) : "f"(x), "f"(y));
    return d;
}
__device__ __forceinline__ void f2un(float& x, float& y, unsigned long long v) {
    asm("mov.b64 {%0, %1}, %2;" : "=f"(x), "=f"(y) : "l"(v));
}
__device__ __forceinline__ unsigned long long fma2(unsigned long long a,
                                                   unsigned long long b,
                                                   unsigned long long c) {
    unsigned long long d;
    asm("fma.rn.f32x2 %0, %1, %2, %3;" : "=l"(d) : "l"(a), "l"(b), "l"(c));
    return d;
}
__device__ __forceinline__ void cp16(uint32_t smem_dst, const void* gsrc) {
    asm volatile("cp.async.cg.shared.global [%0], [%1], 16;\n" ::
                 "r"(smem_dst), "l"(gsrc));
}

// ============================================================
// K1: per-batch adjacency normalization + edge encoder
// grid 32, block 256, dynamic smem = 128*129*4
// ============================================================
__global__ void k1_prep(const float* __restrict__ inp,
                        const float* __restrict__ We,
                        const float* __restrict__ be) {
    extern __shared__ float s_a[];       // [128][129]
    __shared__ float s_d[128];
    __shared__ float s_we[32];
    __shared__ float s_be[16];
    __shared__ float s_part[2048];
    const int b = blockIdx.x, tid = threadIdx.x;
    const size_t base = (size_t)b * 30 * 128 * ROWc;

    if (tid < 32) s_we[tid] = We[tid];
    if (tid >= 32 && tid < 48) s_be[tid - 32] = be[tid - 32];
    for (int idx = tid; idx < 128 * 128; idx += 256) {
        int i = idx >> 7, j = idx & 127;
        s_a[i * 129 + j] = inp[base + (size_t)i * ROWc + j];
    }
    __syncthreads();

    {
        const int j = tid & 127;
        const int half = tid >> 7;
        float acc[16];
#pragma unroll
        for (int f = 0; f < 16; f++) acc[f] = 0.0f;
        for (int i = half * 64; i < half * 64 + 64; i++) {
            float a = s_a[i * 129 + j];
            const float* ep = inp + base + (size_t)i * ROWc + 128 + 2 * j;
            float e0 = ep[0], e1 = ep[1];
#pragma unroll
            for (int f = 0; f < 16; f++) {
                float v = fmaf(e0, s_we[f], fmaf(e1, s_we[16 + f], s_be[f]));
                v = LEAKY(v);
                acc[f] = fmaf(v, a, acc[f]);
            }
        }
        if (half == 1) {
#pragma unroll
            for (int f = 0; f < 16; f++) s_part[j * 16 + f] = acc[f];
        }
        __syncthreads();
        if (half == 0) {
#pragma unroll
            for (int f = 0; f < 16; f++)
                g_ee[(b * 128 + j) * 16 + f] = acc[f] + s_part[j * 16 + f];
        }
    }
    __syncthreads();

    if (tid < 128) {
        const int i = tid;
        float s = 1.0f;
        for (int j = 0; j < 128; j++)
            if (j != i) s += s_a[i * 129 + j];
        s_d[i] = 1.0f / sqrtf(fmaxf(s, 1.0f));
    }
    __syncthreads();
    for (int idx = tid; idx < 128 * 128; idx += 256) {
        int i = idx >> 7, j = idx & 127;
        float a0 = (i == j) ? 1.0f : s_a[i * 129 + j];
        float v = s_d[i] * a0 * s_d[j];
        s_a[i * 129 + j] = v;
        g_a1[b * 16384 + idx] = v;
    }
    __syncthreads();
    if (tid < 128) {
        const int i = tid;
        float s = 0.0f;
        for (int j = 0; j < 128; j++) s += s_a[i * 129 + j];
        g_rs1[b * 128 + i] = s;
        s_d[i] = 1.0f / sqrtf(fmaxf(s, 1.0f));
    }
    __syncthreads();
    for (int idx = tid; idx < 128 * 128; idx += 256) {
        int i = idx >> 7, j = idx & 127;
        float v = s_d[i] * s_a[i * 129 + j] * s_d[j];
        s_a[i * 129 + j] = v;
        g_a2[b * 16384 + idx] = v;
    }
    __syncthreads();
    if (tid < 128) {
        const int i = tid;
        float s = 0.0f;
        for (int j = 0; j < 128; j++) s += s_a[i * 129 + j];
        g_rs2[b * 128 + i] = s;
    }
}

// ============================================================
// K2: per-(b,t) GCN, 512 threads, f32x2 packed math
// grid (32,10), block 512, dynamic smem = 128*129*4
// ============================================================
__global__ void __launch_bounds__(512)
k2_gcn(const float* __restrict__ inp,
       const float* __restrict__ Wn,
       const float* __restrict__ bn,
       const float* __restrict__ Wg,
       const float* __restrict__ bgl,
       const float* __restrict__ gb) {
    extern __shared__ float s_a[];       // [128][129]
    __shared__ float s_xs[2048];
    __shared__ float s_z[2048];
    __shared__ float s_wgT[2048];        // [l][c][o][f]  (f contiguous)
    __shared__ float s_bgl[128];
    __shared__ float s_gb[64];
    __shared__ float s_wn[80];
    __shared__ float s_bn[16];
    __shared__ float s_rs[256];

    const int b = blockIdx.x, t = blockIdx.y, tid = threadIdx.x;
    // transpose Wg on load: src (lc*16+f)*16+o -> dst (lc*16+o)*16+f
    for (int i = tid; i < 2048; i += 512) {
        int o = i & 15, f = (i >> 4) & 15, lc = i >> 8;
        s_wgT[(lc * 16 + o) * 16 + f] = Wg[i];
    }
    if (tid < 128) s_bgl[tid] = bgl[tid];
    if (tid < 64) s_gb[tid] = gb[tid];
    if (tid < 80) s_wn[tid] = Wn[tid];
    if (tid < 16) s_bn[tid] = bn[tid];
    if (tid < 128) s_rs[tid] = g_rs1[b * 128 + tid];
    if (tid >= 128 && tid < 256) s_rs[tid] = g_rs2[b * 128 + tid - 128];
    for (int idx = tid; idx < 16384; idx += 512) {
        int i = idx >> 7, j = idx & 127;
        s_a[i * 129 + j] = g_a1[b * 16384 + idx];
    }
    __syncthreads();

    const int n = tid & 127;
    const int f0 = (tid >> 7) * 4;   // 4 features per thread

    // xs[n,f] = edge_enc + sum_v leaky(node@Wn + bn)
    {
        float acc[4];
        const float* ee = &g_ee[(b * 128 + n) * 16 + f0];
#pragma unroll
        for (int f = 0; f < 4; f++) acc[f] = ee[f];
#pragma unroll
        for (int v = 0; v < 3; v++) {
            const float* np =
                inp + ((size_t)(b * 30 + t * 3 + v) * 128 + n) * ROWc + 384;
            float nk0 = np[0], nk1 = np[1], nk2 = np[2], nk3 = np[3], nk4 = np[4];
#pragma unroll
            for (int f = 0; f < 4; f++) {
                int fc = f0 + f;
                float s = s_bn[fc];
                s = fmaf(nk0, s_wn[fc], s);
                s = fmaf(nk1, s_wn[16 + fc], s);
                s = fmaf(nk2, s_wn[32 + fc], s);
                s = fmaf(nk3, s_wn[48 + fc], s);
                s = fmaf(nk4, s_wn[64 + fc], s);
                acc[f] += LEAKY(s);
            }
        }
#pragma unroll
        for (int f = 0; f < 4; f++) s_xs[n * 16 + f0 + f] = acc[f];
    }
    __syncthreads();

    // z1 = a1 @ xs  (packed)
    {
        unsigned long long za0 = 0ULL, za1 = 0ULL;
#pragma unroll 8
        for (int m = 0; m < 128; m++) {
            float a = s_a[n * 129 + m];
            unsigned long long ap = f2pk(a, a);
            ulonglong2 x = *(const ulonglong2*)&s_xs[m * 16 + f0];
            za0 = fma2(ap, x.x, za0);
            za1 = fma2(ap, x.y, za1);
        }
        ulonglong2 zo; zo.x = za0; zo.y = za1;
        *(ulonglong2*)&s_z[n * 16 + f0] = zo;
    }
    __syncthreads();

    // layer-1 channel mix (packed dot over f) -> s_xs ; also preload a2
    {
        unsigned long long zp[8];
        ulonglong2 q0 = *(const ulonglong2*)&s_z[n * 16];
        ulonglong2 q1 = *(const ulonglong2*)&s_z[n * 16 + 4];
        ulonglong2 q2 = *(const ulonglong2*)&s_z[n * 16 + 8];
        ulonglong2 q3 = *(const ulonglong2*)&s_z[n * 16 + 12];
        zp[0] = q0.x; zp[1] = q0.y; zp[2] = q1.x; zp[3] = q1.y;
        zp[4] = q2.x; zp[5] = q2.y; zp[6] = q3.x; zp[7] = q3.y;
        float rs4 = 4.0f * s_rs[n];
        float outv[4];
#pragma unroll
        for (int o = 0; o < 4; o++) {
            int oc = f0 + o;
            float sum = 0.0f;
#pragma unroll
            for (int c = 0; c < 4; c++) {
                const unsigned long long* wp =
                    (const unsigned long long*)&s_wgT[(c * 16 + oc) * 16];
                unsigned long long a2v = 0ULL;
#pragma unroll
                for (int i = 0; i < 8; i++) a2v = fma2(zp[i], wp[i], a2v);
                float ux, uy; f2un(ux, uy, a2v);
                float u = ux + uy + fmaf(rs4, s_bgl[c * 16 + oc], s_gb[c * 16 + oc]);
                sum += LEAKY(u);
            }
            outv[o] = sum;
        }
        __syncthreads();   // everyone done reading s_z / old s_xs not needed
#pragma unroll
        for (int o = 0; o < 4; o++) s_xs[n * 16 + f0 + o] = outv[o];
    }
    // swap in a2 (s_a free: z1 matmul done)
    for (int idx = tid; idx < 16384; idx += 512) {
        int i = idx >> 7, j = idx & 127;
        s_a[i * 129 + j] = g_a2[b * 16384 + idx];
    }
    __syncthreads();

    // z2 = a2 @ xs2
    {
        unsigned long long za0 = 0ULL, za1 = 0ULL;
#pragma unroll 8
        for (int m = 0; m < 128; m++) {
            float a = s_a[n * 129 + m];
            unsigned long long ap = f2pk(a, a);
            ulonglong2 x = *(const ulonglong2*)&s_xs[m * 16 + f0];
            za0 = fma2(ap, x.x, za0);
            za1 = fma2(ap, x.y, za1);
        }
        ulonglong2 zo; zo.x = za0; zo.y = za1;
        *(ulonglong2*)&s_z[n * 16 + f0] = zo;
    }
    __syncthreads();

    // layer-2 channel mix -> g_x2 (all 4 channels)
    {
        unsigned long long zp[8];
        ulonglong2 q0 = *(const ulonglong2*)&s_z[n * 16];
        ulonglong2 q1 = *(const ulonglong2*)&s_z[n * 16 + 4];
        ulonglong2 q2 = *(const ulonglong2*)&s_z[n * 16 + 8];
        ulonglong2 q3 = *(const ulonglong2*)&s_z[n * 16 + 12];
        zp[0] = q0.x; zp[1] = q0.y; zp[2] = q1.x; zp[3] = q1.y;
        zp[4] = q2.x; zp[5] = q2.y; zp[6] = q3.x; zp[7] = q3.y;
        float rs4 = 4.0f * s_rs[128 + n];
        size_t obase = ((size_t)(b * 10 + t) * 4) * 2048 + n * 16;
#pragma unroll
        for (int o = 0; o < 4; o++) {
            int oc = f0 + o;
#pragma unroll
            for (int c = 0; c < 4; c++) {
                const unsigned long long* wp =
                    (const unsigned long long*)&s_wgT[((4 + c) * 16 + oc) * 16];
                unsigned long long a2v = 0ULL;
#pragma unroll
                for (int i = 0; i < 8; i++) a2v = fma2(zp[i], wp[i], a2v);
                float ux, uy; f2un(ux, uy, a2v);
                float u = ux + uy +
                          fmaf(rs4, s_bgl[64 + c * 16 + oc], s_gb[c * 16 + oc]);
                g_x2[obase + c * 2048 + oc] = LEAKY(u);
            }
        }
    }
}

// ============================================================
// K3: reduce over t -> flat
// ============================================================
__global__ void k3_reduce() {
    int idx = blockIdx.x * 256 + threadIdx.x;
    int b = idx >> 13;
    int j = idx & 8191;
    const float* p = &g_x2[(size_t)b * 10 * 8192 + j];
    float s = 0.0f;
#pragma unroll
    for (int t = 0; t < 10; t++) s += p[(size_t)t * 8192];
    g_flat[idx] = s;
}

// ============================================================
// K4 v3: flat(32x8192) @ W(8192x2048) x2 heads.
// Block 128 = 2 colgroups x 2 rowhalves; W staged via cp.async smem;
// 16-row f32x2 register accumulators. grid (8, 32, 2).
// ============================================================
__global__ void __launch_bounds__(128, 4)
k4_gemm(const float* __restrict__ Wc1, const float* __restrict__ Wa1) {
    __shared__ float s_w[32 * 256];     // 32 KB  [k][col]
    __shared__ float4 s_fd[32 * 16];    // 8 KB   [row][kp] duplicated pairs
    const int tid = threadIdx.x;
    const int head = blockIdx.z;
    const float* __restrict__ W = head ? Wa1 : Wc1;
    const int colbase = blockIdx.x * 256;
    const int warp = tid >> 5, lane = tid & 31;
    const int rhalf = warp & 1;                       // 16-row half
    const int wcol = (warp >> 1) * 128 + lane * 4;    // col within tile
    const int kbase = blockIdx.y * 256;

    const uint32_t sw_base = (uint32_t)__cvta_generic_to_shared(s_w);

    unsigned long long acc[16][2];
#pragma unroll
    for (int r = 0; r < 16; r++) { acc[r][0] = 0ULL; acc[r][1] = 0ULL; }

    for (int stage = 0; stage < 8; stage++) {
        const int k0 = kbase + stage * 32;
        __syncthreads();
        // W tile 32x256 via cp.async (16 x 16B per thread, coalesced)
        {
            const float4* Wg4 = (const float4*)&W[(size_t)k0 * 2048 + colbase];
#pragma unroll
            for (int i = 0; i < 16; i++) {
                int idx = tid + i * 128;          // 0..2047 float4s
                int kk = idx >> 6, cc = idx & 63;
                cp16(sw_base + (uint32_t)(kk * 64 + cc) * 16,
                     &Wg4[kk * 512 + cc]);
            }
            asm volatile("cp.async.commit_group;\n");
        }
        // flat tile duplicated: [row][kp] layout, conflict-free STS.64
#pragma unroll
        for (int i = 0; i < 8; i++) {
            int idx = tid + i * 128;              // 0..1023
            int kk = idx & 31, r = idx >> 5;
            float v = g_flat[r * 8192 + k0 + kk];
            ((float2*)&s_fd[r * 16 + (kk >> 1)])[kk & 1] = make_float2(v, v);
        }
        asm volatile("cp.async.wait_group 0;\n" ::: "memory");
        __syncthreads();

#pragma unroll 4
        for (int kp = 0; kp < 16; kp++) {
            const int k = kp * 2;
            ulonglong2 w0 = *(const ulonglong2*)&s_w[k * 256 + wcol];
            ulonglong2 w1 = *(const ulonglong2*)&s_w[(k + 1) * 256 + wcol];
#pragma unroll
            for (int r = 0; r < 16; r++) {
                ulonglong2 d =
                    *(const ulonglong2*)&s_fd[(rhalf * 16 + r) * 16 + kp];
                acc[r][0] = fma2(d.x, w0.x, acc[r][0]);
                acc[r][1] = fma2(d.x, w0.y, acc[r][1]);
                acc[r][0] = fma2(d.y, w1.x, acc[r][0]);
                acc[r][1] = fma2(d.y, w1.y, acc[r][1]);
            }
        }
    }

    const size_t base = ((size_t)(head * KSPLIT + blockIdx.y)) * 65536;
    const int gcol = colbase + wcol;
#pragma unroll
    for (int r = 0; r < 16; r++) {
        float4 o;
        f2un(o.x, o.y, acc[r][0]);
        f2un(o.z, o.w, acc[r][1]);
        *(float4*)&g_part2[base + (size_t)(rhalf * 16 + r) * 2048 + gcol] = o;
    }
}

// ============================================================
// K5a: reduce K-split partials + bias + leaky
// ============================================================
__global__ void k5a_act(const float* __restrict__ bc1,
                        const float* __restrict__ ba1) {
    const int head = blockIdx.y;
    const int i = blockIdx.x * 256 + threadIdx.x;
    float s = (head ? ba1 : bc1)[i & 2047];
    const size_t hb = (size_t)head * KSPLIT * 65536;
#pragma unroll
    for (int p = 0; p < KSPLIT; p++) s += g_part2[hb + (size_t)p * 65536 + i];
    g_hh[head * 65536 + i] = LEAKY(s);
}

// ============================================================
// K5b: small heads -> critic | actor. grid 32, block 256
// ============================================================
__global__ void k5b_heads(const float* __restrict__ Wc2,
                          const float* __restrict__ bc2,
                          const float* __restrict__ Wc3,
                          const float* __restrict__ bc3,
                          const float* __restrict__ Wa2,
                          const float* __restrict__ ba2,
                          float* __restrict__ out) {
    __shared__ float s_h[2048];
    __shared__ float s_ha[2048];
    __shared__ float s_w[256 * 17];
    __shared__ float s_r[32];
    const int b = blockIdx.x, tid = threadIdx.x;
    for (int i = tid; i < 2048; i += 256) {
        s_h[i] = g_hh[b * 2048 + i];
        s_ha[i] = g_hh[65536 + b * 2048 + i];
    }
    const int w = tid >> 5, lane = tid & 31;
    float psc[2] = {0.0f, 0.0f}, psa[2] = {0.0f, 0.0f};

    for (int c = 0; c < 8; c++) {
        __syncthreads();
        for (int idx = tid; idx < 4096; idx += 256) {
            int k = idx >> 4, f = idx & 15;
            s_w[k * 17 + f] = Wc2[c * 4096 + idx];
        }
        __syncthreads();
#pragma unroll
        for (int dd = 0; dd < 2; dd++) {
            const int f = w + dd * 8;
            float s = 0.0f;
#pragma unroll
            for (int ki = 0; ki < 8; ki++) {
                int k = ki * 32 + lane;
                s = fmaf(s_h[c * 256 + k], s_w[k * 17 + f], s);
            }
            psc[dd] += s;
        }
        __syncthreads();
        for (int idx = tid; idx < 4096; idx += 256) {
            int k = idx >> 4, f = idx & 15;
            s_w[k * 17 + f] = Wa2[c * 4096 + idx];
        }
        __syncthreads();
#pragma unroll
        for (int dd = 0; dd < 2; dd++) {
            const int f = w + dd * 8;
            float s = 0.0f;
#pragma unroll
            for (int ki = 0; ki < 8; ki++) {
                int k = ki * 32 + lane;
                s = fmaf(s_ha[c * 256 + k], s_w[k * 17 + f], s);
            }
            psa[dd] += s;
        }
    }
#pragma unroll
    for (int dd = 0; dd < 2; dd++) {
        float sc = psc[dd], sa = psa[dd];
#pragma unroll
        for (int off = 16; off; off >>= 1) {
            sc += __shfl_down_sync(0xffffffffu, sc, off);
            sa += __shfl_down_sync(0xffffffffu, sa, off);
        }
        if (lane == 0) {
            int f = w + dd * 8;
            float vc = sc + bc2[f];
            float va = sa + ba2[f];
            s_r[f] = LEAKY(vc);
            s_r[16 + f] = LEAKY(va);
        }
    }
    __syncthreads();
    if (tid == 0) {
        float cr = bc3[0];
#pragma unroll
        for (int f = 0; f < 16; f++) cr = fmaf(s_r[f], Wc3[f], cr);
        out[b] = cr;
    }
    if (tid < 16) out[32 + b * 16 + tid] = s_r[16 + tid];
}

// ============================================================
extern "C" void kernel_launch(void* const* d_in, const int* in_sizes, int n_in,
                              void* d_out, int out_size) {
    (void)in_sizes; (void)n_in; (void)out_size;
    const float* inp = (const float*)d_in[0];
    const float* We  = (const float*)d_in[1];
    const float* be  = (const float*)d_in[2];
    const float* Wn  = (const float*)d_in[3];
    const float* bn  = (const float*)d_in[4];
    const float* Wg  = (const float*)d_in[5];
    const float* bgl = (const float*)d_in[6];
    const float* gb  = (const float*)d_in[7];
    const float* Wc1 = (const float*)d_in[8];
    const float* bc1 = (const float*)d_in[9];
    const float* Wc2 = (const float*)d_in[10];
    const float* bc2 = (const float*)d_in[11];
    const float* Wc3 = (const float*)d_in[12];
    const float* bc3 = (const float*)d_in[13];
    const float* Wa1 = (const float*)d_in[14];
    const float* ba1 = (const float*)d_in[15];
    const float* Wa2 = (const float*)d_in[16];
    const float* ba2 = (const float*)d_in[17];

    const int dyn = 128 * 129 * 4;  // 66048 B
    cudaFuncSetAttribute(k1_prep, cudaFuncAttributeMaxDynamicSharedMemorySize, dyn);
    cudaFuncSetAttribute(k2_gcn, cudaFuncAttributeMaxDynamicSharedMemorySize, dyn);

    k1_prep<<<32, 256, dyn>>>(inp, We, be);
    k2_gcn<<<dim3(32, 10), 512, dyn>>>(inp, Wn, bn, Wg, bgl, gb);
    k3_reduce<<<1024, 256>>>();
    k4_gemm<<<dim3(8, KSPLIT, 2), 128>>>(Wc1, Wa1);
    k5a_act<<<dim3(256, 2), 256>>>(bc1, ba1);
    k5b_heads<<<32, 256>>>(Wc2, bc2, Wc3, bc3, Wa2, ba2, (float*)d_out);
}

// round 5
// speedup vs baseline: 2.9623x; 1.1226x over previous
#include <cuda_runtime.h>
#include <cstdint>
#include <cstddef>

// ---------------- problem dims ----------------
// B=32, T=10, NOV=3, N=128, F=16, NF=5, EF=2, C=4, SL=2, HID=2048
#define LEAKY(x) ((x) > 0.0f ? (x) : 0.01f * (x))

constexpr int Bc = 32;
constexpr int Nc = 128;
constexpr int HIDc = 2048;
constexpr int ROWc = 389;      // 3N+NF
constexpr int FLATc = 8192;    // C*N*F
constexpr int KSPLIT = 32;     // k4 K-split factor

// ---------------- scratch (__device__ globals; no allocs) ----------------
__device__ float g_a1[Bc * Nc * Nc];
__device__ float g_a2[Bc * Nc * Nc];
__device__ float g_rs1[Bc * Nc];
__device__ float g_rs2[Bc * Nc];
__device__ float g_ee[Bc * Nc * 16];
__device__ float g_x2[(size_t)Bc * 10 * 4 * Nc * 16];
__device__ float g_flat[Bc * FLATc];
__device__ float g_part2[(size_t)2 * KSPLIT * Bc * HIDc];
__device__ float g_hh[2 * Bc * HIDc];

// ---------------- helpers ----------------
__device__ __forceinline__ unsigned long long f2pk(float x, float y) {
    unsigned long long d;
    asm("mov.b64 %0, {%1, %2};" : "=l"(d) : "f"(x), "f"(y));
    return d;
}
__device__ __forceinline__ void f2un(float& x, float& y, unsigned long long v) {
    asm("mov.b64 {%0, %1}, %2;" : "=f"(x), "=f"(y) : "l"(v));
}
__device__ __forceinline__ unsigned long long fma2(unsigned long long a,
                                                   unsigned long long b,
                                                   unsigned long long c) {
    unsigned long long d;
    asm("fma.rn.f32x2 %0, %1, %2, %3;" : "=l"(d) : "l"(a), "l"(b), "l"(c));
    return d;
}
__device__ __forceinline__ void cp16(uint32_t smem_dst, const void* gsrc) {
    asm volatile("cp.async.cg.shared.global [%0], [%1], 16;\n" ::
                 "r"(smem_dst), "l"(gsrc));
}
__device__ __forceinline__ void cp4(uint32_t smem_dst, const void* gsrc) {
    asm volatile("cp.async.ca.shared.global [%0], [%1], 4;\n" ::
                 "r"(smem_dst), "l"(gsrc));
}
__device__ __forceinline__ void cp_commit() {
    asm volatile("cp.async.commit_group;\n");
}
__device__ __forceinline__ void cp_wait0() {
    asm volatile("cp.async.wait_group 0;\n" ::: "memory");
}

// ============================================================
// K1: per-batch adjacency normalization + edge encoder
// grid 32, block 512, dynamic smem = 128*129*4
// ============================================================
__global__ void __launch_bounds__(512)
k1_prep(const float* __restrict__ inp,
        const float* __restrict__ We,
        const float* __restrict__ be) {
    extern __shared__ float s_a[];       // [128][129]
    __shared__ float s_d[128];
    __shared__ float s_we[32];
    __shared__ float s_be[16];
    __shared__ float s_part[3 * 2048];   // reductions
    const int b = blockIdx.x, tid = threadIdx.x;
    const size_t base = (size_t)b * 30 * 128 * ROWc;

    if (tid < 32) s_we[tid] = We[tid];
    if (tid >= 32 && tid < 48) s_be[tid - 32] = be[tid - 32];
    for (int idx = tid; idx < 128 * 128; idx += 512) {
        int i = idx >> 7, j = idx & 127;
        s_a[i * 129 + j] = inp[base + (size_t)i * ROWc + j];
    }
    __syncthreads();

    // edge encoder: 4-way i-split, smem reduce
    {
        const int j = tid & 127;
        const int q = tid >> 7;      // 0..3
        float acc[16];
#pragma unroll
        for (int f = 0; f < 16; f++) acc[f] = 0.0f;
#pragma unroll 4
        for (int i = q * 32; i < q * 32 + 32; i++) {
            float a = s_a[i * 129 + j];
            const float* ep = inp + base + (size_t)i * ROWc + 128 + 2 * j;
            float e0 = ep[0], e1 = ep[1];
#pragma unroll
            for (int f = 0; f < 16; f++) {
                float v = fmaf(e0, s_we[f], fmaf(e1, s_we[16 + f], s_be[f]));
                v = LEAKY(v);
                acc[f] = fmaf(v, a, acc[f]);
            }
        }
        if (q) {
#pragma unroll
            for (int f = 0; f < 16; f++)
                s_part[(q - 1) * 2048 + j * 16 + f] = acc[f];
        }
        __syncthreads();
        if (q == 0) {
#pragma unroll
            for (int f = 0; f < 16; f++)
                g_ee[(b * 128 + j) * 16 + f] =
                    acc[f] + s_part[j * 16 + f] + s_part[2048 + j * 16 + f] +
                    s_part[4096 + j * 16 + f];
        }
    }
    __syncthreads();

    // deg0 (diag treated as 1), 4 threads per row
    {
        const int i = tid & 127, q = tid >> 7;
        float p = 0.0f;
        for (int j = q * 32; j < q * 32 + 32; j++)
            p += (j == i) ? 1.0f : s_a[i * 129 + j];
        s_part[q * 128 + i] = p;
        __syncthreads();
        if (tid < 128) {
            float s = s_part[tid] + s_part[128 + tid] + s_part[256 + tid] +
                      s_part[384 + tid];
            s_d[tid] = 1.0f / sqrtf(fmaxf(s, 1.0f));
        }
        __syncthreads();
    }
    // a1 = d0_i * a0 * d0_j
    for (int idx = tid; idx < 128 * 128; idx += 512) {
        int i = idx >> 7, j = idx & 127;
        float a0 = (i == j) ? 1.0f : s_a[i * 129 + j];
        float v = s_d[i] * a0 * s_d[j];
        s_a[i * 129 + j] = v;
        g_a1[b * 16384 + idx] = v;
    }
    __syncthreads();
    // rs1 + d1
    {
        const int i = tid & 127, q = tid >> 7;
        float p = 0.0f;
        for (int j = q * 32; j < q * 32 + 32; j++) p += s_a[i * 129 + j];
        s_part[q * 128 + i] = p;
        __syncthreads();
        if (tid < 128) {
            float s = s_part[tid] + s_part[128 + tid] + s_part[256 + tid] +
                      s_part[384 + tid];
            g_rs1[b * 128 + tid] = s;
            s_d[tid] = 1.0f / sqrtf(fmaxf(s, 1.0f));
        }
        __syncthreads();
    }
    // a2
    for (int idx = tid; idx < 128 * 128; idx += 512) {
        int i = idx >> 7, j = idx & 127;
        float v = s_d[i] * s_a[i * 129 + j] * s_d[j];
        s_a[i * 129 + j] = v;
        g_a2[b * 16384 + idx] = v;
    }
    __syncthreads();
    // rs2
    {
        const int i = tid & 127, q = tid >> 7;
        float p = 0.0f;
        for (int j = q * 32; j < q * 32 + 32; j++) p += s_a[i * 129 + j];
        s_part[q * 128 + i] = p;
        __syncthreads();
        if (tid < 128)
            g_rs2[b * 128 + tid] = s_part[tid] + s_part[128 + tid] +
                                   s_part[256 + tid] + s_part[384 + tid];
    }
}

// ============================================================
// K2: per-(b,t) GCN, 512 threads, f32x2 packed math,
// a1/a2 loads overlapped via cp.async.
// grid (32,10), block 512, dynamic smem = 128*129*4
// ============================================================
__global__ void __launch_bounds__(512)
k2_gcn(const float* __restrict__ inp,
       const float* __restrict__ Wn,
       const float* __restrict__ bn,
       const float* __restrict__ Wg,
       const float* __restrict__ bgl,
       const float* __restrict__ gb) {
    extern __shared__ float s_a[];       // [128][129]
    __shared__ float s_xs[2048];
    __shared__ float s_z[2048];
    __shared__ float s_wgT[2048];        // [l][c][o][f]  (f contiguous)
    __shared__ float s_bgl[128];
    __shared__ float s_gb[64];
    __shared__ float s_wn[80];
    __shared__ float s_bn[16];
    __shared__ float s_rs[256];

    const int b = blockIdx.x, t = blockIdx.y, tid = threadIdx.x;
    const uint32_t sa_base = (uint32_t)__cvta_generic_to_shared(s_a);

    // start a1 copy ASAP (overlaps weight loads + node encoder)
    for (int idx = tid; idx < 16384; idx += 512) {
        int i = idx >> 7, j = idx & 127;
        cp4(sa_base + (uint32_t)(i * 129 + j) * 4, &g_a1[b * 16384 + idx]);
    }
    cp_commit();

    for (int i = tid; i < 2048; i += 512) {
        int o = i & 15, f = (i >> 4) & 15, lc = i >> 8;
        s_wgT[(lc * 16 + o) * 16 + f] = Wg[i];
    }
    if (tid < 128) s_bgl[tid] = bgl[tid];
    if (tid < 64) s_gb[tid] = gb[tid];
    if (tid < 80) s_wn[tid] = Wn[tid];
    if (tid < 16) s_bn[tid] = bn[tid];
    if (tid < 128) s_rs[tid] = g_rs1[b * 128 + tid];
    if (tid >= 128 && tid < 256) s_rs[tid] = g_rs2[b * 128 + tid - 128];
    __syncthreads();    // weights visible

    const int n = tid & 127;
    const int f0 = (tid >> 7) * 4;

    // xs[n,f] = edge_enc + sum_v leaky(node@Wn + bn)
    {
        float acc[4];
        const float* ee = &g_ee[(b * 128 + n) * 16 + f0];
#pragma unroll
        for (int f = 0; f < 4; f++) acc[f] = ee[f];
#pragma unroll
        for (int v = 0; v < 3; v++) {
            const float* np =
                inp + ((size_t)(b * 30 + t * 3 + v) * 128 + n) * ROWc + 384;
            float nk0 = np[0], nk1 = np[1], nk2 = np[2], nk3 = np[3], nk4 = np[4];
#pragma unroll
            for (int f = 0; f < 4; f++) {
                int fc = f0 + f;
                float s = s_bn[fc];
                s = fmaf(nk0, s_wn[fc], s);
                s = fmaf(nk1, s_wn[16 + fc], s);
                s = fmaf(nk2, s_wn[32 + fc], s);
                s = fmaf(nk3, s_wn[48 + fc], s);
                s = fmaf(nk4, s_wn[64 + fc], s);
                acc[f] += LEAKY(s);
            }
        }
#pragma unroll
        for (int f = 0; f < 4; f++) s_xs[n * 16 + f0 + f] = acc[f];
    }
    cp_wait0();
    __syncthreads();    // a1 + s_xs visible

    // z1 = a1 @ xs  (packed)
    {
        unsigned long long za0 = 0ULL, za1 = 0ULL;
#pragma unroll 8
        for (int m = 0; m < 128; m++) {
            float a = s_a[n * 129 + m];
            unsigned long long ap = f2pk(a, a);
            ulonglong2 x = *(const ulonglong2*)&s_xs[m * 16 + f0];
            za0 = fma2(ap, x.x, za0);
            za1 = fma2(ap, x.y, za1);
        }
        ulonglong2 zo; zo.x = za0; zo.y = za1;
        *(ulonglong2*)&s_z[n * 16 + f0] = zo;
    }
    __syncthreads();    // z1 done; a1 reads done -> s_a free

    // issue a2 copy now (overlaps layer-1 mix)
    for (int idx = tid; idx < 16384; idx += 512) {
        int i = idx >> 7, j = idx & 127;
        cp4(sa_base + (uint32_t)(i * 129 + j) * 4, &g_a2[b * 16384 + idx]);
    }
    cp_commit();

    // layer-1 channel mix (packed dot over f) -> s_xs
    {
        unsigned long long zp[8];
        ulonglong2 q0 = *(const ulonglong2*)&s_z[n * 16];
        ulonglong2 q1 = *(const ulonglong2*)&s_z[n * 16 + 4];
        ulonglong2 q2 = *(const ulonglong2*)&s_z[n * 16 + 8];
        ulonglong2 q3 = *(const ulonglong2*)&s_z[n * 16 + 12];
        zp[0] = q0.x; zp[1] = q0.y; zp[2] = q1.x; zp[3] = q1.y;
        zp[4] = q2.x; zp[5] = q2.y; zp[6] = q3.x; zp[7] = q3.y;
        float rs4 = 4.0f * s_rs[n];
        float outv[4];
#pragma unroll
        for (int o = 0; o < 4; o++) {
            int oc = f0 + o;
            float sum = 0.0f;
#pragma unroll
            for (int c = 0; c < 4; c++) {
                const unsigned long long* wp =
                    (const unsigned long long*)&s_wgT[(c * 16 + oc) * 16];
                unsigned long long a2v = 0ULL;
#pragma unroll
                for (int i = 0; i < 8; i++) a2v = fma2(zp[i], wp[i], a2v);
                float ux, uy; f2un(ux, uy, a2v);
                float u = ux + uy + fmaf(rs4, s_bgl[c * 16 + oc], s_gb[c * 16 + oc]);
                sum += LEAKY(u);
            }
            outv[o] = sum;
        }
#pragma unroll
        for (int o = 0; o < 4; o++) s_xs[n * 16 + f0 + o] = outv[o];
    }
    cp_wait0();
    __syncthreads();    // a2 + new s_xs visible

    // z2 = a2 @ xs2
    {
        unsigned long long za0 = 0ULL, za1 = 0ULL;
#pragma unroll 8
        for (int m = 0; m < 128; m++) {
            float a = s_a[n * 129 + m];
            unsigned long long ap = f2pk(a, a);
            ulonglong2 x = *(const ulonglong2*)&s_xs[m * 16 + f0];
            za0 = fma2(ap, x.x, za0);
            za1 = fma2(ap, x.y, za1);
        }
        ulonglong2 zo; zo.x = za0; zo.y = za1;
        *(ulonglong2*)&s_z[n * 16 + f0] = zo;
    }
    __syncthreads();

    // layer-2 channel mix -> g_x2
    {
        unsigned long long zp[8];
        ulonglong2 q0 = *(const ulonglong2*)&s_z[n * 16];
        ulonglong2 q1 = *(const ulonglong2*)&s_z[n * 16 + 4];
        ulonglong2 q2 = *(const ulonglong2*)&s_z[n * 16 + 8];
        ulonglong2 q3 = *(const ulonglong2*)&s_z[n * 16 + 12];
        zp[0] = q0.x; zp[1] = q0.y; zp[2] = q1.x; zp[3] = q1.y;
        zp[4] = q2.x; zp[5] = q2.y; zp[6] = q3.x; zp[7] = q3.y;
        float rs4 = 4.0f * s_rs[128 + n];
        size_t obase = ((size_t)(b * 10 + t) * 4) * 2048 + n * 16;
#pragma unroll
        for (int o = 0; o < 4; o++) {
            int oc = f0 + o;
#pragma unroll
            for (int c = 0; c < 4; c++) {
                const unsigned long long* wp =
                    (const unsigned long long*)&s_wgT[((4 + c) * 16 + oc) * 16];
                unsigned long long a2v = 0ULL;
#pragma unroll
                for (int i = 0; i < 8; i++) a2v = fma2(zp[i], wp[i], a2v);
                float ux, uy; f2un(ux, uy, a2v);
                float u = ux + uy +
                          fmaf(rs4, s_bgl[64 + c * 16 + oc], s_gb[c * 16 + oc]);
                g_x2[obase + c * 2048 + oc] = LEAKY(u);
            }
        }
    }
}

// ============================================================
// K3: reduce over t -> flat
// ============================================================
__global__ void k3_reduce() {
    int idx = blockIdx.x * 256 + threadIdx.x;
    int b = idx >> 13;
    int j = idx & 8191;
    const float* p = &g_x2[(size_t)b * 10 * 8192 + j];
    float s = 0.0f;
#pragma unroll
    for (int t = 0; t < 10; t++) s += p[(size_t)t * 8192];
    g_flat[idx] = s;
}

// ============================================================
// K4 v4: flat(32x8192) @ W(8192x2048) x2 heads.
// Double-buffered cp.async pipeline, K=16 stages.
// grid (8, 32, 2), block 128, 4 CTAs/SM.
// ============================================================
__global__ void __launch_bounds__(128, 4)
k4_gemm(const float* __restrict__ Wc1, const float* __restrict__ Wa1) {
    __shared__ float s_w[2][16][256];     // 32 KB
    __shared__ float4 s_fd[2][32][9];     // padded pitch 9
    const int tid = threadIdx.x;
    const int head = blockIdx.z;
    const float* __restrict__ W = head ? Wa1 : Wc1;
    const int colbase = blockIdx.x * 256;
    const int warp = tid >> 5, lane = tid & 31;
    const int rhalf = warp & 1;
    const int wcol = (warp >> 1) * 128 + lane * 4;
    const int kbase = blockIdx.y * 256;

    const int frow = tid >> 2;        // 0..31
    const int fks = (tid & 3) * 4;    // 0,4,8,12
    const int fkp = fks >> 1;         // 0,2,4,6

    const uint32_t sw0 = (uint32_t)__cvta_generic_to_shared(&s_w[0][0][0]);
    const uint32_t sw1 = (uint32_t)__cvta_generic_to_shared(&s_w[1][0][0]);

    unsigned long long acc[16][2];
#pragma unroll
    for (int r = 0; r < 16; r++) { acc[r][0] = 0ULL; acc[r][1] = 0ULL; }

    // prologue: stage-0 fills
    {
        const float4* Wg4 = (const float4*)&W[(size_t)kbase * 2048 + colbase];
#pragma unroll
        for (int i = 0; i < 8; i++) {
            int idx = tid + i * 128;
            int kk = idx >> 6, cc = idx & 63;
            cp16(sw0 + (uint32_t)(kk * 256 + cc * 4) * 4,
                 &Wg4[(size_t)kk * 512 + cc]);
        }
        cp_commit();
        float4 fv = *(const float4*)&g_flat[frow * 8192 + kbase + fks];
        s_fd[0][frow][fkp] = make_float4(fv.x, fv.x, fv.y, fv.y);
        s_fd[0][frow][fkp + 1] = make_float4(fv.z, fv.z, fv.w, fv.w);
    }
    float4 fvn = *(const float4*)&g_flat[frow * 8192 + kbase + 16 + fks];

    for (int s = 0; s < 16; s++) {
        const int b = s & 1;
        cp_wait0();
        __syncthreads();    // stage-s buffers ready; stage s-1 compute done
        if (s < 15) {
            const int kn = kbase + (s + 1) * 16;
            const uint32_t swn = b ? sw0 : sw1;
            const int nb = b ^ 1;
            const float4* Wg4 = (const float4*)&W[(size_t)kn * 2048 + colbase];
#pragma unroll
            for (int i = 0; i < 8; i++) {
                int idx = tid + i * 128;
                int kk = idx >> 6, cc = idx & 63;
                cp16(swn + (uint32_t)(kk * 256 + cc * 4) * 4,
                     &Wg4[(size_t)kk * 512 + cc]);
            }
            cp_commit();
            s_fd[nb][frow][fkp] = make_float4(fvn.x, fvn.x, fvn.y, fvn.y);
            s_fd[nb][frow][fkp + 1] = make_float4(fvn.z, fvn.z, fvn.w, fvn.w);
            if (s < 14)
                fvn = *(const float4*)&g_flat[frow * 8192 + kbase +
                                              (s + 2) * 16 + fks];
        }
#pragma unroll
        for (int kp = 0; kp < 8; kp++) {
            ulonglong2 w0 = *(const ulonglong2*)&s_w[b][kp * 2][wcol];
            ulonglong2 w1 = *(const ulonglong2*)&s_w[b][kp * 2 + 1][wcol];
#pragma unroll
            for (int r = 0; r < 16; r++) {
                ulonglong2 d =
                    *(const ulonglong2*)&s_fd[b][rhalf * 16 + r][kp];
                acc[r][0] = fma2(d.x, w0.x, acc[r][0]);
                acc[r][1] = fma2(d.x, w0.y, acc[r][1]);
                acc[r][0] = fma2(d.y, w1.x, acc[r][0]);
                acc[r][1] = fma2(d.y, w1.y, acc[r][1]);
            }
        }
    }

    const size_t base = ((size_t)(head * KSPLIT + blockIdx.y)) * 65536;
    const int gcol = colbase + wcol;
#pragma unroll
    for (int r = 0; r < 16; r++) {
        float4 o;
        f2un(o.x, o.y, acc[r][0]);
        f2un(o.z, o.w, acc[r][1]);
        *(float4*)&g_part2[base + (size_t)(rhalf * 16 + r) * 2048 + gcol] = o;
    }
}

// ============================================================
// K5a: reduce K-split partials + bias + leaky
// ============================================================
__global__ void k5a_act(const float* __restrict__ bc1,
                        const float* __restrict__ ba1) {
    const int head = blockIdx.y;
    const int i = blockIdx.x * 256 + threadIdx.x;
    float s = (head ? ba1 : bc1)[i & 2047];
    const size_t hb = (size_t)head * KSPLIT * 65536;
#pragma unroll
    for (int p = 0; p < KSPLIT; p++) s += g_part2[hb + (size_t)p * 65536 + i];
    g_hh[head * 65536 + i] = LEAKY(s);
}

// ============================================================
// K5b: small heads -> critic | actor. grid 32, block 256
// ============================================================
__global__ void k5b_heads(const float* __restrict__ Wc2,
                          const float* __restrict__ bc2,
                          const float* __restrict__ Wc3,
                          const float* __restrict__ bc3,
                          const float* __restrict__ Wa2,
                          const float* __restrict__ ba2,
                          float* __restrict__ out) {
    __shared__ float s_h[2048];
    __shared__ float s_ha[2048];
    __shared__ float s_w[256 * 17];
    __shared__ float s_r[32];
    const int b = blockIdx.x, tid = threadIdx.x;
    for (int i = tid; i < 2048; i += 256) {
        s_h[i] = g_hh[b * 2048 + i];
        s_ha[i] = g_hh[65536 + b * 2048 + i];
    }
    const int w = tid >> 5, lane = tid & 31;
    float psc[2] = {0.0f, 0.0f}, psa[2] = {0.0f, 0.0f};

    for (int c = 0; c < 8; c++) {
        __syncthreads();
        for (int idx = tid; idx < 4096; idx += 256) {
            int k = idx >> 4, f = idx & 15;
            s_w[k * 17 + f] = Wc2[c * 4096 + idx];
        }
        __syncthreads();
#pragma unroll
        for (int dd = 0; dd < 2; dd++) {
            const int f = w + dd * 8;
            float s = 0.0f;
#pragma unroll
            for (int ki = 0; ki < 8; ki++) {
                int k = ki * 32 + lane;
                s = fmaf(s_h[c * 256 + k], s_w[k * 17 + f], s);
            }
            psc[dd] += s;
        }
        __syncthreads();
        for (int idx = tid; idx < 4096; idx += 256) {
            int k = idx >> 4, f = idx & 15;
            s_w[k * 17 + f] = Wa2[c * 4096 + idx];
        }
        __syncthreads();
#pragma unroll
        for (int dd = 0; dd < 2; dd++) {
            const int f = w + dd * 8;
            float s = 0.0f;
#pragma unroll
            for (int ki = 0; ki < 8; ki++) {
                int k = ki * 32 + lane;
                s = fmaf(s_ha[c * 256 + k], s_w[k * 17 + f], s);
            }
            psa[dd] += s;
        }
    }
#pragma unroll
    for (int dd = 0; dd < 2; dd++) {
        float sc = psc[dd], sa = psa[dd];
#pragma unroll
        for (int off = 16; off; off >>= 1) {
            sc += __shfl_down_sync(0xffffffffu, sc, off);
            sa += __shfl_down_sync(0xffffffffu, sa, off);
        }
        if (lane == 0) {
            int f = w + dd * 8;
            float vc = sc + bc2[f];
            float va = sa + ba2[f];
            s_r[f] = LEAKY(vc);
            s_r[16 + f] = LEAKY(va);
        }
    }
    __syncthreads();
    if (tid == 0) {
        float cr = bc3[0];
#pragma unroll
        for (int f = 0; f < 16; f++) cr = fmaf(s_r[f], Wc3[f], cr);
        out[b] = cr;
    }
    if (tid < 16) out[32 + b * 16 + tid] = s_r[16 + tid];
}

// ============================================================
extern "C" void kernel_launch(void* const* d_in, const int* in_sizes, int n_in,
                              void* d_out, int out_size) {
    (void)in_sizes; (void)n_in; (void)out_size;
    const float* inp = (const float*)d_in[0];
    const float* We  = (const float*)d_in[1];
    const float* be  = (const float*)d_in[2];
    const float* Wn  = (const float*)d_in[3];
    const float* bn  = (const float*)d_in[4];
    const float* Wg  = (const float*)d_in[5];
    const float* bgl = (const float*)d_in[6];
    const float* gb  = (const float*)d_in[7];
    const float* Wc1 = (const float*)d_in[8];
    const float* bc1 = (const float*)d_in[9];
    const float* Wc2 = (const float*)d_in[10];
    const float* bc2 = (const float*)d_in[11];
    const float* Wc3 = (const float*)d_in[12];
    const float* bc3 = (const float*)d_in[13];
    const float* Wa1 = (const float*)d_in[14];
    const float* ba1 = (const float*)d_in[15];
    const float* Wa2 = (const float*)d_in[16];
    const float* ba2 = (const float*)d_in[17];

    const int dyn = 128 * 129 * 4;  // 66048 B
    cudaFuncSetAttribute(k1_prep, cudaFuncAttributeMaxDynamicSharedMemorySize, dyn);
    cudaFuncSetAttribute(k2_gcn, cudaFuncAttributeMaxDynamicSharedMemorySize, dyn);

    k1_prep<<<32, 512, dyn>>>(inp, We, be);
    k2_gcn<<<dim3(32, 10), 512, dyn>>>(inp, Wn, bn, Wg, bgl, gb);
    k3_reduce<<<1024, 256>>>();
    k4_gemm<<<dim3(8, KSPLIT, 2), 128>>>(Wc1, Wa1);
    k5a_act<<<dim3(256, 2), 256>>>(bc1, ba1);
    k5b_heads<<<32, 256>>>(Wc2, bc2, Wc3, bc3, Wa2, ba2, (float*)d_out);
}

// round 6
// speedup vs baseline: 3.5837x; 1.2097x over previous
#include <cuda_runtime.h>
#include <cstdint>
#include <cstddef>

// ---------------- problem dims ----------------
// B=32, T=10, NOV=3, N=128, F=16, NF=5, EF=2, C=4, SL=2, HID=2048
#define LEAKY(x) ((x) > 0.0f ? (x) : 0.01f * (x))

constexpr int Bc = 32;
constexpr int Nc = 128;
constexpr int HIDc = 2048;
constexpr int ROWc = 389;      // 3N+NF
constexpr int FLATc = 8192;    // C*N*F
constexpr int KSPLIT = 32;     // k4 K-split factor

// ---------------- scratch (__device__ globals; no allocs) ----------------
__device__ float g_a1[Bc * Nc * Nc];
__device__ float g_a2[Bc * Nc * Nc];
__device__ float g_rs1[Bc * Nc];
__device__ float g_rs2[Bc * Nc];
__device__ float g_ee[Bc * Nc * 16];
__device__ float g_x2[(size_t)Bc * 10 * 4 * Nc * 16];
__device__ float g_flat[Bc * FLATc];
__device__ float g_part2[(size_t)2 * KSPLIT * Bc * HIDc];
__device__ float g_hh[2 * Bc * HIDc];

// ---------------- helpers ----------------
__device__ __forceinline__ unsigned long long f2pk(float x, float y) {
    unsigned long long d;
    asm("mov.b64 %0, {%1, %2};" : "=l"(d) : "f"(x), "f"(y));
    return d;
}
__device__ __forceinline__ void f2un(float& x, float& y, unsigned long long v) {
    asm("mov.b64 {%0, %1}, %2;" : "=f"(x), "=f"(y) : "l"(v));
}
__device__ __forceinline__ unsigned long long fma2(unsigned long long a,
                                                   unsigned long long b,
                                                   unsigned long long c) {
    unsigned long long d;
    asm("fma.rn.f32x2 %0, %1, %2, %3;" : "=l"(d) : "l"(a), "l"(b), "l"(c));
    return d;
}
__device__ __forceinline__ void cp16(uint32_t smem_dst, const void* gsrc) {
    asm volatile("cp.async.cg.shared.global [%0], [%1], 16;\n" ::
                 "r"(smem_dst), "l"(gsrc));
}
__device__ __forceinline__ void cp4(uint32_t smem_dst, const void* gsrc) {
    asm volatile("cp.async.ca.shared.global [%0], [%1], 4;\n" ::
                 "r"(smem_dst), "l"(gsrc));
}
__device__ __forceinline__ void cp_commit() {
    asm volatile("cp.async.commit_group;\n");
}
__device__ __forceinline__ void cp_wait0() {
    asm volatile("cp.async.wait_group 0;\n" ::: "memory");
}

// ============================================================
// K1: per-batch adjacency normalization + edge encoder
// grid 32, block 512, dynamic smem = 128*129*4
// ============================================================
__global__ void __launch_bounds__(512)
k1_prep(const float* __restrict__ inp,
        const float* __restrict__ We,
        const float* __restrict__ be) {
    extern __shared__ float s_a[];       // [128][129]
    __shared__ float s_d[128];
    __shared__ float s_we[32];
    __shared__ float s_be[16];
    __shared__ float s_part[3 * 2048];
    const int b = blockIdx.x, tid = threadIdx.x;
    const size_t base = (size_t)b * 30 * 128 * ROWc;

    if (tid < 32) s_we[tid] = We[tid];
    if (tid >= 32 && tid < 48) s_be[tid - 32] = be[tid - 32];
    for (int idx = tid; idx < 128 * 128; idx += 512) {
        int i = idx >> 7, j = idx & 127;
        s_a[i * 129 + j] = inp[base + (size_t)i * ROWc + j];
    }
    __syncthreads();

    // edge encoder: 4-way i-split, smem reduce
    {
        const int j = tid & 127;
        const int q = tid >> 7;
        float acc[16];
#pragma unroll
        for (int f = 0; f < 16; f++) acc[f] = 0.0f;
#pragma unroll 4
        for (int i = q * 32; i < q * 32 + 32; i++) {
            float a = s_a[i * 129 + j];
            const float* ep = inp + base + (size_t)i * ROWc + 128 + 2 * j;
            float e0 = ep[0], e1 = ep[1];
#pragma unroll
            for (int f = 0; f < 16; f++) {
                float v = fmaf(e0, s_we[f], fmaf(e1, s_we[16 + f], s_be[f]));
                v = LEAKY(v);
                acc[f] = fmaf(v, a, acc[f]);
            }
        }
        if (q) {
#pragma unroll
            for (int f = 0; f < 16; f++)
                s_part[(q - 1) * 2048 + j * 16 + f] = acc[f];
        }
        __syncthreads();
        if (q == 0) {
#pragma unroll
            for (int f = 0; f < 16; f++)
                g_ee[(b * 128 + j) * 16 + f] =
                    acc[f] + s_part[j * 16 + f] + s_part[2048 + j * 16 + f] +
                    s_part[4096 + j * 16 + f];
        }
    }
    __syncthreads();

    {
        const int i = tid & 127, q = tid >> 7;
        float p = 0.0f;
        for (int j = q * 32; j < q * 32 + 32; j++)
            p += (j == i) ? 1.0f : s_a[i * 129 + j];
        s_part[q * 128 + i] = p;
        __syncthreads();
        if (tid < 128) {
            float s = s_part[tid] + s_part[128 + tid] + s_part[256 + tid] +
                      s_part[384 + tid];
            s_d[tid] = 1.0f / sqrtf(fmaxf(s, 1.0f));
        }
        __syncthreads();
    }
    for (int idx = tid; idx < 128 * 128; idx += 512) {
        int i = idx >> 7, j = idx & 127;
        float a0 = (i == j) ? 1.0f : s_a[i * 129 + j];
        float v = s_d[i] * a0 * s_d[j];
        s_a[i * 129 + j] = v;
        g_a1[b * 16384 + idx] = v;
    }
    __syncthreads();
    {
        const int i = tid & 127, q = tid >> 7;
        float p = 0.0f;
        for (int j = q * 32; j < q * 32 + 32; j++) p += s_a[i * 129 + j];
        s_part[q * 128 + i] = p;
        __syncthreads();
        if (tid < 128) {
            float s = s_part[tid] + s_part[128 + tid] + s_part[256 + tid] +
                      s_part[384 + tid];
            g_rs1[b * 128 + tid] = s;
            s_d[tid] = 1.0f / sqrtf(fmaxf(s, 1.0f));
        }
        __syncthreads();
    }
    for (int idx = tid; idx < 128 * 128; idx += 512) {
        int i = idx >> 7, j = idx & 127;
        float v = s_d[i] * s_a[i * 129 + j] * s_d[j];
        s_a[i * 129 + j] = v;
        g_a2[b * 16384 + idx] = v;
    }
    __syncthreads();
    {
        const int i = tid & 127, q = tid >> 7;
        float p = 0.0f;
        for (int j = q * 32; j < q * 32 + 32; j++) p += s_a[i * 129 + j];
        s_part[q * 128 + i] = p;
        __syncthreads();
        if (tid < 128)
            g_rs2[b * 128 + tid] = s_part[tid] + s_part[128 + tid] +
                                   s_part[256 + tid] + s_part[384 + tid];
    }
}

// ============================================================
// K2: per-(b,t) GCN, 512 threads, f32x2 packed math,
// a1/a2 loads overlapped via cp.async.
// grid (32,10), block 512, dynamic smem = 128*129*4
// ============================================================
__global__ void __launch_bounds__(512)
k2_gcn(const float* __restrict__ inp,
       const float* __restrict__ Wn,
       const float* __restrict__ bn,
       const float* __restrict__ Wg,
       const float* __restrict__ bgl,
       const float* __restrict__ gb) {
    extern __shared__ float s_a[];       // [128][129]
    __shared__ float s_xs[2048];
    __shared__ float s_z[2048];
    __shared__ float s_wgT[2048];        // [l][c][o][f]
    __shared__ float s_bgl[128];
    __shared__ float s_gb[64];
    __shared__ float s_wn[80];
    __shared__ float s_bn[16];
    __shared__ float s_rs[256];

    const int b = blockIdx.x, t = blockIdx.y, tid = threadIdx.x;
    const uint32_t sa_base = (uint32_t)__cvta_generic_to_shared(s_a);

    for (int idx = tid; idx < 16384; idx += 512) {
        int i = idx >> 7, j = idx & 127;
        cp4(sa_base + (uint32_t)(i * 129 + j) * 4, &g_a1[b * 16384 + idx]);
    }
    cp_commit();

    for (int i = tid; i < 2048; i += 512) {
        int o = i & 15, f = (i >> 4) & 15, lc = i >> 8;
        s_wgT[(lc * 16 + o) * 16 + f] = Wg[i];
    }
    if (tid < 128) s_bgl[tid] = bgl[tid];
    if (tid < 64) s_gb[tid] = gb[tid];
    if (tid < 80) s_wn[tid] = Wn[tid];
    if (tid < 16) s_bn[tid] = bn[tid];
    if (tid < 128) s_rs[tid] = g_rs1[b * 128 + tid];
    if (tid >= 128 && tid < 256) s_rs[tid] = g_rs2[b * 128 + tid - 128];
    __syncthreads();

    const int n = tid & 127;
    const int f0 = (tid >> 7) * 4;

    // xs = edge_enc + sum_v leaky(node@Wn + bn)
    {
        float acc[4];
        const float* ee = &g_ee[(b * 128 + n) * 16 + f0];
#pragma unroll
        for (int f = 0; f < 4; f++) acc[f] = ee[f];
#pragma unroll
        for (int v = 0; v < 3; v++) {
            const float* np =
                inp + ((size_t)(b * 30 + t * 3 + v) * 128 + n) * ROWc + 384;
            float nk0 = np[0], nk1 = np[1], nk2 = np[2], nk3 = np[3], nk4 = np[4];
#pragma unroll
            for (int f = 0; f < 4; f++) {
                int fc = f0 + f;
                float s = s_bn[fc];
                s = fmaf(nk0, s_wn[fc], s);
                s = fmaf(nk1, s_wn[16 + fc], s);
                s = fmaf(nk2, s_wn[32 + fc], s);
                s = fmaf(nk3, s_wn[48 + fc], s);
                s = fmaf(nk4, s_wn[64 + fc], s);
                acc[f] += LEAKY(s);
            }
        }
        *(float4*)&s_xs[n * 16 + f0] = make_float4(acc[0], acc[1], acc[2], acc[3]);
    }
    cp_wait0();
    __syncthreads();

    // z1 = a1 @ xs
    {
        unsigned long long za0 = 0ULL, za1 = 0ULL;
#pragma unroll 8
        for (int m = 0; m < 128; m++) {
            float a = s_a[n * 129 + m];
            unsigned long long ap = f2pk(a, a);
            ulonglong2 x = *(const ulonglong2*)&s_xs[m * 16 + f0];
            za0 = fma2(ap, x.x, za0);
            za1 = fma2(ap, x.y, za1);
        }
        ulonglong2 zo; zo.x = za0; zo.y = za1;
        *(ulonglong2*)&s_z[n * 16 + f0] = zo;
    }
    __syncthreads();

    // a2 copy overlaps layer-1 mix
    for (int idx = tid; idx < 16384; idx += 512) {
        int i = idx >> 7, j = idx & 127;
        cp4(sa_base + (uint32_t)(i * 129 + j) * 4, &g_a2[b * 16384 + idx]);
    }
    cp_commit();

    // layer-1 channel mix
    {
        unsigned long long zp[8];
        ulonglong2 q0 = *(const ulonglong2*)&s_z[n * 16];
        ulonglong2 q1 = *(const ulonglong2*)&s_z[n * 16 + 4];
        ulonglong2 q2 = *(const ulonglong2*)&s_z[n * 16 + 8];
        ulonglong2 q3 = *(const ulonglong2*)&s_z[n * 16 + 12];
        zp[0] = q0.x; zp[1] = q0.y; zp[2] = q1.x; zp[3] = q1.y;
        zp[4] = q2.x; zp[5] = q2.y; zp[6] = q3.x; zp[7] = q3.y;
        float rs4 = 4.0f * s_rs[n];
        float outv[4];
#pragma unroll
        for (int o = 0; o < 4; o++) {
            int oc = f0 + o;
            float sum = 0.0f;
#pragma unroll
            for (int c = 0; c < 4; c++) {
                const unsigned long long* wp =
                    (const unsigned long long*)&s_wgT[(c * 16 + oc) * 16];
                unsigned long long a2v = 0ULL;
#pragma unroll
                for (int i = 0; i < 8; i++) a2v = fma2(zp[i], wp[i], a2v);
                float ux, uy; f2un(ux, uy, a2v);
                float u = ux + uy + fmaf(rs4, s_bgl[c * 16 + oc], s_gb[c * 16 + oc]);
                sum += LEAKY(u);
            }
            outv[o] = sum;
        }
        *(float4*)&s_xs[n * 16 + f0] =
            make_float4(outv[0], outv[1], outv[2], outv[3]);
    }
    cp_wait0();
    __syncthreads();

    // z2 = a2 @ xs2
    {
        unsigned long long za0 = 0ULL, za1 = 0ULL;
#pragma unroll 8
        for (int m = 0; m < 128; m++) {
            float a = s_a[n * 129 + m];
            unsigned long long ap = f2pk(a, a);
            ulonglong2 x = *(const ulonglong2*)&s_xs[m * 16 + f0];
            za0 = fma2(ap, x.x, za0);
            za1 = fma2(ap, x.y, za1);
        }
        ulonglong2 zo; zo.x = za0; zo.y = za1;
        *(ulonglong2*)&s_z[n * 16 + f0] = zo;
    }
    __syncthreads();

    // layer-2 channel mix -> g_x2 (float4 stores)
    {
        unsigned long long zp[8];
        ulonglong2 q0 = *(const ulonglong2*)&s_z[n * 16];
        ulonglong2 q1 = *(const ulonglong2*)&s_z[n * 16 + 4];
        ulonglong2 q2 = *(const ulonglong2*)&s_z[n * 16 + 8];
        ulonglong2 q3 = *(const ulonglong2*)&s_z[n * 16 + 12];
        zp[0] = q0.x; zp[1] = q0.y; zp[2] = q1.x; zp[3] = q1.y;
        zp[4] = q2.x; zp[5] = q2.y; zp[6] = q3.x; zp[7] = q3.y;
        float rs4 = 4.0f * s_rs[128 + n];
        size_t obase = ((size_t)(b * 10 + t) * 4) * 2048 + n * 16 + f0;
#pragma unroll
        for (int c = 0; c < 4; c++) {
            float ov[4];
#pragma unroll
            for (int o = 0; o < 4; o++) {
                int oc = f0 + o;
                const unsigned long long* wp =
                    (const unsigned long long*)&s_wgT[((4 + c) * 16 + oc) * 16];
                unsigned long long a2v = 0ULL;
#pragma unroll
                for (int i = 0; i < 8; i++) a2v = fma2(zp[i], wp[i], a2v);
                float ux, uy; f2un(ux, uy, a2v);
                float u = ux + uy +
                          fmaf(rs4, s_bgl[64 + c * 16 + oc], s_gb[c * 16 + oc]);
                ov[o] = LEAKY(u);
            }
            *(float4*)&g_x2[obase + c * 2048] =
                make_float4(ov[0], ov[1], ov[2], ov[3]);
        }
    }
}

// ============================================================
// K3: reduce over t -> flat (float4). grid 256, block 256
// ============================================================
__global__ void k3_reduce() {
    int idx4 = blockIdx.x * 256 + threadIdx.x;   // 0..65535
    int b = idx4 >> 11;
    int j4 = idx4 & 2047;
    const float4* p = (const float4*)&g_x2[(size_t)b * 10 * 8192] + j4;
    float4 s = make_float4(0.f, 0.f, 0.f, 0.f);
#pragma unroll
    for (int t = 0; t < 10; t++) {
        float4 v = p[t * 2048];
        s.x += v.x; s.y += v.y; s.z += v.z; s.w += v.w;
    }
    ((float4*)g_flat)[idx4] = s;
}

// ============================================================
// K4 v5: flat(32x8192) @ W(8192x2048) x2 heads.
// 128-col x 256-k CTA tile, 8 CTAs/SM, double-buffered cp.async.
// grid (16, 32, 2) = 1024 CTAs, block 128.
// ============================================================
__global__ void __launch_bounds__(128, 8)
k4_gemm(const float* __restrict__ Wc1, const float* __restrict__ Wa1) {
    __shared__ float s_w[2][16][128];     // 16 KB
    __shared__ float4 s_fd[2][32][9];     // 9 KB
    const int tid = threadIdx.x;
    const int head = blockIdx.z;
    const float* __restrict__ W = head ? Wa1 : Wc1;
    const int colbase = blockIdx.x * 128;
    const int rq = tid >> 5;              // row-quarter (8 rows)
    const int lane = tid & 31;
    const int wcol = lane * 4;
    const int kbase = blockIdx.y * 256;

    const int frow = tid >> 2;
    const int fks = (tid & 3) * 4;
    const int fkp = fks >> 1;

    const uint32_t sw0 = (uint32_t)__cvta_generic_to_shared(&s_w[0][0][0]);
    const uint32_t sw1 = (uint32_t)__cvta_generic_to_shared(&s_w[1][0][0]);

    unsigned long long acc[8][2];
#pragma unroll
    for (int r = 0; r < 8; r++) { acc[r][0] = 0ULL; acc[r][1] = 0ULL; }

    // prologue: stage-0 fills
    {
        const float4* Wg4 = (const float4*)&W[(size_t)kbase * 2048 + colbase];
#pragma unroll
        for (int i = 0; i < 4; i++) {
            int idx = tid + i * 128;              // 0..511 float4s
            int kk = idx >> 5, cc = idx & 31;
            cp16(sw0 + (uint32_t)(kk * 128 + cc * 4) * 4,
                 &Wg4[(size_t)kk * 512 + cc]);
        }
        cp_commit();
        float4 fv = *(const float4*)&g_flat[frow * 8192 + kbase + fks];
        s_fd[0][frow][fkp] = make_float4(fv.x, fv.x, fv.y, fv.y);
        s_fd[0][frow][fkp + 1] = make_float4(fv.z, fv.z, fv.w, fv.w);
    }
    float4 fvn = *(const float4*)&g_flat[frow * 8192 + kbase + 16 + fks];

    for (int s = 0; s < 16; s++) {
        const int b = s & 1;
        cp_wait0();
        __syncthreads();
        if (s < 15) {
            const int kn = kbase + (s + 1) * 16;
            const uint32_t swn = b ? sw0 : sw1;
            const int nb = b ^ 1;
            const float4* Wg4 = (const float4*)&W[(size_t)kn * 2048 + colbase];
#pragma unroll
            for (int i = 0; i < 4; i++) {
                int idx = tid + i * 128;
                int kk = idx >> 5, cc = idx & 31;
                cp16(swn + (uint32_t)(kk * 128 + cc * 4) * 4,
                     &Wg4[(size_t)kk * 512 + cc]);
            }
            cp_commit();
            s_fd[nb][frow][fkp] = make_float4(fvn.x, fvn.x, fvn.y, fvn.y);
            s_fd[nb][frow][fkp + 1] = make_float4(fvn.z, fvn.z, fvn.w, fvn.w);
            if (s < 14)
                fvn = *(const float4*)&g_flat[frow * 8192 + kbase +
                                              (s + 2) * 16 + fks];
        }
#pragma unroll
        for (int kp = 0; kp < 8; kp++) {
            ulonglong2 w0 = *(const ulonglong2*)&s_w[b][kp * 2][wcol];
            ulonglong2 w1 = *(const ulonglong2*)&s_w[b][kp * 2 + 1][wcol];
#pragma unroll
            for (int r = 0; r < 8; r++) {
                ulonglong2 d = *(const ulonglong2*)&s_fd[b][rq * 8 + r][kp];
                acc[r][0] = fma2(d.x, w0.x, acc[r][0]);
                acc[r][1] = fma2(d.x, w0.y, acc[r][1]);
                acc[r][0] = fma2(d.y, w1.x, acc[r][0]);
                acc[r][1] = fma2(d.y, w1.y, acc[r][1]);
            }
        }
    }

    const size_t base = ((size_t)(head * KSPLIT + blockIdx.y)) * 65536;
    const int gcol = colbase + wcol;
#pragma unroll
    for (int r = 0; r < 8; r++) {
        float4 o;
        f2un(o.x, o.y, acc[r][0]);
        f2un(o.z, o.w, acc[r][1]);
        *(float4*)&g_part2[base + (size_t)(rq * 8 + r) * 2048 + gcol] = o;
    }
}

// ============================================================
// K5a: reduce K-split partials + bias + leaky (float4)
// grid (64, 2), block 256
// ============================================================
__global__ void k5a_act(const float* __restrict__ bc1,
                        const float* __restrict__ ba1) {
    const int head = blockIdx.y;
    const int i4 = blockIdx.x * 256 + threadIdx.x;   // 0..16383
    const int col4 = i4 & 511;
    float4 s = ((const float4*)(head ? ba1 : bc1))[col4];
    const float4* p = (const float4*)&g_part2[(size_t)head * KSPLIT * 65536];
#pragma unroll
    for (int pi = 0; pi < KSPLIT; pi++) {
        float4 v = p[(size_t)pi * 16384 + i4];
        s.x += v.x; s.y += v.y; s.z += v.z; s.w += v.w;
    }
    s.x = LEAKY(s.x); s.y = LEAKY(s.y); s.z = LEAKY(s.z); s.w = LEAKY(s.w);
    ((float4*)g_hh)[head * 16384 + i4] = s;
}

// ============================================================
// K5b: small heads, per-head CTAs + W2 prefetch.
// grid (32, 2), block 256
// ============================================================
__global__ void k5b_heads(const float* __restrict__ Wc2,
                          const float* __restrict__ bc2,
                          const float* __restrict__ Wc3,
                          const float* __restrict__ bc3,
                          const float* __restrict__ Wa2,
                          const float* __restrict__ ba2,
                          float* __restrict__ out) {
    __shared__ float s_h[2048];
    __shared__ float s_w[256 * 17];
    __shared__ float s_r[16];
    const int b = blockIdx.x, head = blockIdx.y, tid = threadIdx.x;
    const float* __restrict__ W2 = head ? Wa2 : Wc2;
    const float* __restrict__ b2 = head ? ba2 : bc2;

    {
        const float4* hs = (const float4*)&g_hh[head * 65536 + b * 2048];
        ((float4*)s_h)[tid] = hs[tid];
        ((float4*)s_h)[tid + 256] = hs[tid + 256];
    }
    const int w = tid >> 5, lane = tid & 31;
    float ps[2] = {0.0f, 0.0f};

    // prefetch chunk 0
    float rv[16];
#pragma unroll
    for (int i = 0; i < 16; i++) rv[i] = W2[tid + i * 256];

    for (int c = 0; c < 8; c++) {
        __syncthreads();
#pragma unroll
        for (int i = 0; i < 16; i++) {
            int idx = tid + i * 256;
            s_w[(idx >> 4) * 17 + (idx & 15)] = rv[i];
        }
        __syncthreads();
        if (c < 7) {
#pragma unroll
            for (int i = 0; i < 16; i++)
                rv[i] = W2[(c + 1) * 4096 + tid + i * 256];
        }
#pragma unroll
        for (int dd = 0; dd < 2; dd++) {
            const int f = w + dd * 8;
            float s = 0.0f;
#pragma unroll
            for (int ki = 0; ki < 8; ki++) {
                int k = ki * 32 + lane;
                s = fmaf(s_h[c * 256 + k], s_w[k * 17 + f], s);
            }
            ps[dd] += s;
        }
    }
#pragma unroll
    for (int dd = 0; dd < 2; dd++) {
        float s = ps[dd];
#pragma unroll
        for (int off = 16; off; off >>= 1) s += __shfl_down_sync(0xffffffffu, s, off);
        if (lane == 0) {
            int f = w + dd * 8;
            float v = s + b2[f];
            s_r[f] = LEAKY(v);
        }
    }
    __syncthreads();
    if (head == 0) {
        if (tid == 0) {
            float cr = bc3[0];
#pragma unroll
            for (int f = 0; f < 16; f++) cr = fmaf(s_r[f], Wc3[f], cr);
            out[b] = cr;
        }
    } else {
        if (tid < 16) out[32 + b * 16 + tid] = s_r[tid];
    }
}

// ============================================================
extern "C" void kernel_launch(void* const* d_in, const int* in_sizes, int n_in,
                              void* d_out, int out_size) {
    (void)in_sizes; (void)n_in; (void)out_size;
    const float* inp = (const float*)d_in[0];
    const float* We  = (const float*)d_in[1];
    const float* be  = (const float*)d_in[2];
    const float* Wn  = (const float*)d_in[3];
    const float* bn  = (const float*)d_in[4];
    const float* Wg  = (const float*)d_in[5];
    const float* bgl = (const float*)d_in[6];
    const float* gb  = (const float*)d_in[7];
    const float* Wc1 = (const float*)d_in[8];
    const float* bc1 = (const float*)d_in[9];
    const float* Wc2 = (const float*)d_in[10];
    const float* bc2 = (const float*)d_in[11];
    const float* Wc3 = (const float*)d_in[12];
    const float* bc3 = (const float*)d_in[13];
    const float* Wa1 = (const float*)d_in[14];
    const float* ba1 = (const float*)d_in[15];
    const float* Wa2 = (const float*)d_in[16];
    const float* ba2 = (const float*)d_in[17];

    const int dyn = 128 * 129 * 4;  // 66048 B
    cudaFuncSetAttribute(k1_prep, cudaFuncAttributeMaxDynamicSharedMemorySize, dyn);
    cudaFuncSetAttribute(k2_gcn, cudaFuncAttributeMaxDynamicSharedMemorySize, dyn);

    k1_prep<<<32, 512, dyn>>>(inp, We, be);
    k2_gcn<<<dim3(32, 10), 512, dyn>>>(inp, Wn, bn, Wg, bgl, gb);
    k3_reduce<<<256, 256>>>();
    k4_gemm<<<dim3(16, KSPLIT, 2), 128>>>(Wc1, Wa1);
    k5a_act<<<dim3(64, 2), 256>>>(bc1, ba1);
    k5b_heads<<<dim3(32, 2), 256>>>(Wc2, bc2, Wc3, bc3, Wa2, ba2, (float*)d_out);
}

// round 8
// speedup vs baseline: 3.7890x; 1.0573x over previous
#include <cuda_runtime.h>
#include <cstdint>
#include <cstddef>

// ---------------- problem dims ----------------
// B=32, T=10, NOV=3, N=128, F=16, NF=5, EF=2, C=4, SL=2, HID=2048
#define LEAKY(x) ((x) > 0.0f ? (x) : 0.01f * (x))

constexpr int Bc = 32;
constexpr int Nc = 128;
constexpr int HIDc = 2048;
constexpr int ROWc = 389;      // 3N+NF
constexpr int FLATc = 8192;    // C*N*F
constexpr int KSPLIT = 32;     // k4 K-split factor

// ---------------- scratch (__device__ globals; no allocs) ----------------
__device__ float g_a1[Bc * Nc * Nc];
__device__ float g_a2[Bc * Nc * Nc];
__device__ float g_rs1[Bc * Nc];
__device__ float g_rs2[Bc * Nc];
__device__ float g_ee[Bc * Nc * 16];
__device__ float g_x2[(size_t)Bc * 10 * 4 * Nc * 16];
__device__ float g_flat[Bc * FLATc];
__device__ float g_part2[(size_t)2 * KSPLIT * Bc * HIDc];
__device__ float g_hh[2 * Bc * HIDc];

// ---------------- helpers ----------------
__device__ __forceinline__ unsigned long long f2pk(float x, float y) {
    unsigned long long d;
    asm("mov.b64 %0, {%1, %2};" : "=l"(d) : "f"(x), "f"(y));
    return d;
}
__device__ __forceinline__ void f2un(float& x, float& y, unsigned long long v) {
    asm("mov.b64 {%0, %1}, %2;" : "=f"(x), "=f"(y) : "l"(v));
}
__device__ __forceinline__ unsigned long long fma2(unsigned long long a,
                                                   unsigned long long b,
                                                   unsigned long long c) {
    unsigned long long d;
    asm("fma.rn.f32x2 %0, %1, %2, %3;" : "=l"(d) : "l"(a), "l"(b), "l"(c));
    return d;
}
__device__ __forceinline__ void cp16(uint32_t smem_dst, const void* gsrc) {
    asm volatile("cp.async.cg.shared.global [%0], [%1], 16;\n" ::
                 "r"(smem_dst), "l"(gsrc));
}
__device__ __forceinline__ void cp4(uint32_t smem_dst, const void* gsrc) {
    asm volatile("cp.async.ca.shared.global [%0], [%1], 4;\n" ::
                 "r"(smem_dst), "l"(gsrc));
}
__device__ __forceinline__ void cp_commit() {
    asm volatile("cp.async.commit_group;\n");
}
__device__ __forceinline__ void cp_wait0() {
    asm volatile("cp.async.wait_group 0;\n" ::: "memory");
}

// ============================================================
// K1: per-batch adjacency normalization + edge encoder
// grid 32, block 512, dynamic smem = 128*129*4
// ============================================================
__global__ void __launch_bounds__(512)
k1_prep(const float* __restrict__ inp,
        const float* __restrict__ We,
        const float* __restrict__ be) {
    extern __shared__ float s_a[];       // [128][129]
    __shared__ float s_d[128];
    __shared__ float s_we[32];
    __shared__ float s_be[16];
    __shared__ float s_part[3 * 2048];
    const int b = blockIdx.x, tid = threadIdx.x;
    const size_t base = (size_t)b * 30 * 128 * ROWc;

    if (tid < 32) s_we[tid] = We[tid];
    if (tid >= 32 && tid < 48) s_be[tid - 32] = be[tid - 32];
    for (int idx = tid; idx < 128 * 128; idx += 512) {
        int i = idx >> 7, j = idx & 127;
        s_a[i * 129 + j] = inp[base + (size_t)i * ROWc + j];
    }
    __syncthreads();

    // edge encoder: 4-way i-split, smem reduce
    {
        const int j = tid & 127;
        const int q = tid >> 7;
        float acc[16];
#pragma unroll
        for (int f = 0; f < 16; f++) acc[f] = 0.0f;
#pragma unroll 4
        for (int i = q * 32; i < q * 32 + 32; i++) {
            float a = s_a[i * 129 + j];
            const float* ep = inp + base + (size_t)i * ROWc + 128 + 2 * j;
            float e0 = ep[0], e1 = ep[1];
#pragma unroll
            for (int f = 0; f < 16; f++) {
                float v = fmaf(e0, s_we[f], fmaf(e1, s_we[16 + f], s_be[f]));
                v = LEAKY(v);
                acc[f] = fmaf(v, a, acc[f]);
            }
        }
        if (q) {
#pragma unroll
            for (int f = 0; f < 16; f++)
                s_part[(q - 1) * 2048 + j * 16 + f] = acc[f];
        }
        __syncthreads();
        if (q == 0) {
#pragma unroll
            for (int f = 0; f < 16; f++)
                g_ee[(b * 128 + j) * 16 + f] =
                    acc[f] + s_part[j * 16 + f] + s_part[2048 + j * 16 + f] +
                    s_part[4096 + j * 16 + f];
        }
    }
    __syncthreads();

    {
        const int i = tid & 127, q = tid >> 7;
        float p = 0.0f;
        for (int j = q * 32; j < q * 32 + 32; j++)
            p += (j == i) ? 1.0f : s_a[i * 129 + j];
        s_part[q * 128 + i] = p;
        __syncthreads();
        if (tid < 128) {
            float s = s_part[tid] + s_part[128 + tid] + s_part[256 + tid] +
                      s_part[384 + tid];
            s_d[tid] = 1.0f / sqrtf(fmaxf(s, 1.0f));
        }
        __syncthreads();
    }
    for (int idx = tid; idx < 128 * 128; idx += 512) {
        int i = idx >> 7, j = idx & 127;
        float a0 = (i == j) ? 1.0f : s_a[i * 129 + j];
        float v = s_d[i] * a0 * s_d[j];
        s_a[i * 129 + j] = v;
        g_a1[b * 16384 + idx] = v;
    }
    __syncthreads();
    {
        const int i = tid & 127, q = tid >> 7;
        float p = 0.0f;
        for (int j = q * 32; j < q * 32 + 32; j++) p += s_a[i * 129 + j];
        s_part[q * 128 + i] = p;
        __syncthreads();
        if (tid < 128) {
            float s = s_part[tid] + s_part[128 + tid] + s_part[256 + tid] +
                      s_part[384 + tid];
            g_rs1[b * 128 + tid] = s;
            s_d[tid] = 1.0f / sqrtf(fmaxf(s, 1.0f));
        }
        __syncthreads();
    }
    for (int idx = tid; idx < 128 * 128; idx += 512) {
        int i = idx >> 7, j = idx & 127;
        float v = s_d[i] * s_a[i * 129 + j] * s_d[j];
        s_a[i * 129 + j] = v;
        g_a2[b * 16384 + idx] = v;
    }
    __syncthreads();
    {
        const int i = tid & 127, q = tid >> 7;
        float p = 0.0f;
        for (int j = q * 32; j < q * 32 + 32; j++) p += s_a[i * 129 + j];
        s_part[q * 128 + i] = p;
        __syncthreads();
        if (tid < 128)
            g_rs2[b * 128 + tid] = s_part[tid] + s_part[128 + tid] +
                                   s_part[256 + tid] + s_part[384 + tid];
    }
}

// ============================================================
// K2: per-(b,t) GCN, 512 threads, f32x2 packed math,
// a1/a2 loads overlapped via cp.async.
// grid (32,10), block 512, dynamic smem = 128*129*4
// ============================================================
__global__ void __launch_bounds__(512)
k2_gcn(const float* __restrict__ inp,
       const float* __restrict__ Wn,
       const float* __restrict__ bn,
       const float* __restrict__ Wg,
       const float* __restrict__ bgl,
       const float* __restrict__ gb) {
    extern __shared__ float s_a[];       // [128][129]
    __shared__ float s_xs[2048];
    __shared__ float s_z[2048];
    __shared__ float s_wgT[2048];        // [l][c][o][f]
    __shared__ float s_bgl[128];
    __shared__ float s_gb[64];
    __shared__ float s_wn[80];
    __shared__ float s_bn[16];
    __shared__ float s_rs[256];

    const int b = blockIdx.x, t = blockIdx.y, tid = threadIdx.x;
    const uint32_t sa_base = (uint32_t)__cvta_generic_to_shared(s_a);

    for (int idx = tid; idx < 16384; idx += 512) {
        int i = idx >> 7, j = idx & 127;
        cp4(sa_base + (uint32_t)(i * 129 + j) * 4, &g_a1[b * 16384 + idx]);
    }
    cp_commit();

    for (int i = tid; i < 2048; i += 512) {
        int o = i & 15, f = (i >> 4) & 15, lc = i >> 8;
        s_wgT[(lc * 16 + o) * 16 + f] = Wg[i];
    }
    if (tid < 128) s_bgl[tid] = bgl[tid];
    if (tid < 64) s_gb[tid] = gb[tid];
    if (tid < 80) s_wn[tid] = Wn[tid];
    if (tid < 16) s_bn[tid] = bn[tid];
    if (tid < 128) s_rs[tid] = g_rs1[b * 128 + tid];
    if (tid >= 128 && tid < 256) s_rs[tid] = g_rs2[b * 128 + tid - 128];
    __syncthreads();

    const int n = tid & 127;
    const int f0 = (tid >> 7) * 4;

    // xs = edge_enc + sum_v leaky(node@Wn + bn)
    {
        float acc[4];
        const float* ee = &g_ee[(b * 128 + n) * 16 + f0];
#pragma unroll
        for (int f = 0; f < 4; f++) acc[f] = ee[f];
#pragma unroll
        for (int v = 0; v < 3; v++) {
            const float* np =
                inp + ((size_t)(b * 30 + t * 3 + v) * 128 + n) * ROWc + 384;
            float nk0 = np[0], nk1 = np[1], nk2 = np[2], nk3 = np[3], nk4 = np[4];
#pragma unroll
            for (int f = 0; f < 4; f++) {
                int fc = f0 + f;
                float s = s_bn[fc];
                s = fmaf(nk0, s_wn[fc], s);
                s = fmaf(nk1, s_wn[16 + fc], s);
                s = fmaf(nk2, s_wn[32 + fc], s);
                s = fmaf(nk3, s_wn[48 + fc], s);
                s = fmaf(nk4, s_wn[64 + fc], s);
                acc[f] += LEAKY(s);
            }
        }
        *(float4*)&s_xs[n * 16 + f0] = make_float4(acc[0], acc[1], acc[2], acc[3]);
    }
    cp_wait0();
    __syncthreads();

    // z1 = a1 @ xs
    {
        unsigned long long za0 = 0ULL, za1 = 0ULL;
#pragma unroll 8
        for (int m = 0; m < 128; m++) {
            float a = s_a[n * 129 + m];
            unsigned long long ap = f2pk(a, a);
            ulonglong2 x = *(const ulonglong2*)&s_xs[m * 16 + f0];
            za0 = fma2(ap, x.x, za0);
            za1 = fma2(ap, x.y, za1);
        }
        ulonglong2 zo; zo.x = za0; zo.y = za1;
        *(ulonglong2*)&s_z[n * 16 + f0] = zo;
    }
    __syncthreads();

    // a2 copy overlaps layer-1 mix
    for (int idx = tid; idx < 16384; idx += 512) {
        int i = idx >> 7, j = idx & 127;
        cp4(sa_base + (uint32_t)(i * 129 + j) * 4, &g_a2[b * 16384 + idx]);
    }
    cp_commit();

    // layer-1 channel mix
    {
        unsigned long long zp[8];
        ulonglong2 q0 = *(const ulonglong2*)&s_z[n * 16];
        ulonglong2 q1 = *(const ulonglong2*)&s_z[n * 16 + 4];
        ulonglong2 q2 = *(const ulonglong2*)&s_z[n * 16 + 8];
        ulonglong2 q3 = *(const ulonglong2*)&s_z[n * 16 + 12];
        zp[0] = q0.x; zp[1] = q0.y; zp[2] = q1.x; zp[3] = q1.y;
        zp[4] = q2.x; zp[5] = q2.y; zp[6] = q3.x; zp[7] = q3.y;
        float rs4 = 4.0f * s_rs[n];
        float outv[4];
#pragma unroll
        for (int o = 0; o < 4; o++) {
            int oc = f0 + o;
            float sum = 0.0f;
#pragma unroll
            for (int c = 0; c < 4; c++) {
                const unsigned long long* wp =
                    (const unsigned long long*)&s_wgT[(c * 16 + oc) * 16];
                unsigned long long a2v = 0ULL;
#pragma unroll
                for (int i = 0; i < 8; i++) a2v = fma2(zp[i], wp[i], a2v);
                float ux, uy; f2un(ux, uy, a2v);
                float u = ux + uy + fmaf(rs4, s_bgl[c * 16 + oc], s_gb[c * 16 + oc]);
                sum += LEAKY(u);
            }
            outv[o] = sum;
        }
        *(float4*)&s_xs[n * 16 + f0] =
            make_float4(outv[0], outv[1], outv[2], outv[3]);
    }
    cp_wait0();
    __syncthreads();

    // z2 = a2 @ xs2
    {
        unsigned long long za0 = 0ULL, za1 = 0ULL;
#pragma unroll 8
        for (int m = 0; m < 128; m++) {
            float a = s_a[n * 129 + m];
            unsigned long long ap = f2pk(a, a);
            ulonglong2 x = *(const ulonglong2*)&s_xs[m * 16 + f0];
            za0 = fma2(ap, x.x, za0);
            za1 = fma2(ap, x.y, za1);
        }
        ulonglong2 zo; zo.x = za0; zo.y = za1;
        *(ulonglong2*)&s_z[n * 16 + f0] = zo;
    }
    __syncthreads();

    // layer-2 channel mix -> g_x2 (float4 stores)
    {
        unsigned long long zp[8];
        ulonglong2 q0 = *(const ulonglong2*)&s_z[n * 16];
        ulonglong2 q1 = *(const ulonglong2*)&s_z[n * 16 + 4];
        ulonglong2 q2 = *(const ulonglong2*)&s_z[n * 16 + 8];
        ulonglong2 q3 = *(const ulonglong2*)&s_z[n * 16 + 12];
        zp[0] = q0.x; zp[1] = q0.y; zp[2] = q1.x; zp[3] = q1.y;
        zp[4] = q2.x; zp[5] = q2.y; zp[6] = q3.x; zp[7] = q3.y;
        float rs4 = 4.0f * s_rs[128 + n];
        size_t obase = ((size_t)(b * 10 + t) * 4) * 2048 + n * 16 + f0;
#pragma unroll
        for (int c = 0; c < 4; c++) {
            float ov[4];
#pragma unroll
            for (int o = 0; o < 4; o++) {
                int oc = f0 + o;
                const unsigned long long* wp =
                    (const unsigned long long*)&s_wgT[((4 + c) * 16 + oc) * 16];
                unsigned long long a2v = 0ULL;
#pragma unroll
                for (int i = 0; i < 8; i++) a2v = fma2(zp[i], wp[i], a2v);
                float ux, uy; f2un(ux, uy, a2v);
                float u = ux + uy +
                          fmaf(rs4, s_bgl[64 + c * 16 + oc], s_gb[c * 16 + oc]);
                ov[o] = LEAKY(u);
            }
            *(float4*)&g_x2[obase + c * 2048] =
                make_float4(ov[0], ov[1], ov[2], ov[3]);
        }
    }
}

// ============================================================
// K3: reduce over t -> flat (float4). grid 256, block 256
// ============================================================
__global__ void k3_reduce() {
    int idx4 = blockIdx.x * 256 + threadIdx.x;   // 0..65535
    int b = idx4 >> 11;
    int j4 = idx4 & 2047;
    const float4* p = (const float4*)&g_x2[(size_t)b * 10 * 8192] + j4;
    float4 s = make_float4(0.f, 0.f, 0.f, 0.f);
#pragma unroll
    for (int t = 0; t < 10; t++) {
        float4 v = p[t * 2048];
        s.x += v.x; s.y += v.y; s.z += v.z; s.w += v.w;
    }
    ((float4*)g_flat)[idx4] = s;
}

// ============================================================
// K4 v6: flat(32x8192) @ W(8192x2048) x2 heads.
// Warp = 8-row group; flat stage-tile in REGISTERS (shfl broadcast,
// zero smem traffic for flat). s_w double-buffered cp.async only.
// grid (16, 32, 2) = 1024 CTAs, block 128, 6 CTAs/SM.
// ============================================================
__global__ void __launch_bounds__(128, 6)
k4_gemm(const float* __restrict__ Wc1, const float* __restrict__ Wa1) {
    __shared__ float s_w[2][16][128];     // 16 KB
    const int tid = threadIdx.x;
    const int head = blockIdx.z;
    const float* __restrict__ W = head ? Wa1 : Wc1;
    const int colbase = blockIdx.x * 128;
    const int warp = tid >> 5, lane = tid & 31;
    const int rowbase = warp * 8;
    const int kbase = blockIdx.y * 256;

    // this lane holds flat[rowbase + (lane>>2)][k0 + (lane&3)*4 .. +3]
    const int fr = rowbase + (lane >> 2);
    const int fq = (lane & 3) * 4;

    const uint32_t sw0 = (uint32_t)__cvta_generic_to_shared(&s_w[0][0][0]);
    const uint32_t sw1 = (uint32_t)__cvta_generic_to_shared(&s_w[1][0][0]);

    unsigned long long acc[8][2];
#pragma unroll
    for (int r = 0; r < 8; r++) { acc[r][0] = 0ULL; acc[r][1] = 0ULL; }

    // prologue: stage-0 W tile
    {
#pragma unroll
        for (int i = 0; i < 4; i++) {
            int idx = tid + i * 128;               // 0..511
            int kr = idx >> 5, cq = idx & 31;
            cp16(sw0 + (uint32_t)(kr * 128 + cq * 4) * 4,
                 &W[(size_t)(kbase + kr) * 2048 + colbase + cq * 4]);
        }
        cp_commit();
    }
    float4 fcur = *(const float4*)&g_flat[fr * 8192 + kbase + fq];
    float4 fnext = *(const float4*)&g_flat[fr * 8192 + kbase + 16 + fq];

    for (int s = 0; s < 16; s++) {
        const int b = s & 1;
        cp_wait0();
        __syncthreads();
        if (s < 15) {
            const uint32_t swn = b ? sw0 : sw1;
            const int kn = kbase + (s + 1) * 16;
#pragma unroll
            for (int i = 0; i < 4; i++) {
                int idx = tid + i * 128;
                int kr = idx >> 5, cq = idx & 31;
                cp16(swn + (uint32_t)(kr * 128 + cq * 4) * 4,
                     &W[(size_t)(kn + kr) * 2048 + colbase + cq * 4]);
            }
            cp_commit();
        }
        float fc0 = fcur.x, fc1 = fcur.y, fc2 = fcur.z, fc3 = fcur.w;
#pragma unroll
        for (int kp = 0; kp < 8; kp++) {
            ulonglong2 w0 = *(const ulonglong2*)&s_w[b][kp * 2][lane * 4];
            ulonglong2 w1 = *(const ulonglong2*)&s_w[b][kp * 2 + 1][lane * 4];
            const bool hi = (kp & 1);
#pragma unroll
            for (int r = 0; r < 8; r++) {
                const int src = r * 4 + (kp >> 1);
                float vk = __shfl_sync(0xffffffffu, hi ? fc2 : fc0, src);
                float vk1 = __shfl_sync(0xffffffffu, hi ? fc3 : fc1, src);
                unsigned long long dk = f2pk(vk, vk);
                unsigned long long dk1 = f2pk(vk1, vk1);
                acc[r][0] = fma2(dk, w0.x, acc[r][0]);
                acc[r][1] = fma2(dk, w0.y, acc[r][1]);
                acc[r][0] = fma2(dk1, w1.x, acc[r][0]);
                acc[r][1] = fma2(dk1, w1.y, acc[r][1]);
            }
        }
        fcur = fnext;
        if (s < 14)
            fnext = *(const float4*)&g_flat[fr * 8192 + kbase + (s + 2) * 16 + fq];
    }

    const size_t base = ((size_t)(head * KSPLIT + blockIdx.y)) * 65536;
    const int gcol = colbase + lane * 4;
#pragma unroll
    for (int r = 0; r < 8; r++) {
        float4 o;
        f2un(o.x, o.y, acc[r][0]);
        f2un(o.z, o.w, acc[r][1]);
        *(float4*)&g_part2[base + (size_t)(rowbase + r) * 2048 + gcol] = o;
    }
}

// ============================================================
// K5a: reduce K-split partials + bias + leaky (float4)
// grid (64, 2), block 256
// ============================================================
__global__ void k5a_act(const float* __restrict__ bc1,
                        const float* __restrict__ ba1) {
    const int head = blockIdx.y;
    const int i4 = blockIdx.x * 256 + threadIdx.x;   // 0..16383
    const int col4 = i4 & 511;
    float4 s = ((const float4*)(head ? ba1 : bc1))[col4];
    const float4* p = (const float4*)&g_part2[(size_t)head * KSPLIT * 65536];
#pragma unroll
    for (int pi = 0; pi < KSPLIT; pi++) {
        float4 v = p[(size_t)pi * 16384 + i4];
        s.x += v.x; s.y += v.y; s.z += v.z; s.w += v.w;
    }
    s.x = LEAKY(s.x); s.y = LEAKY(s.y); s.z = LEAKY(s.z); s.w = LEAKY(s.w);
    ((float4*)g_hh)[head * 16384 + i4] = s;
}

// ============================================================
// K5b: small heads, per-head CTAs + W2 prefetch.
// grid (32, 2), block 256
// ============================================================
__global__ void k5b_heads(const float* __restrict__ Wc2,
                          const float* __restrict__ bc2,
                          const float* __restrict__ Wc3,
                          const float* __restrict__ bc3,
                          const float* __restrict__ Wa2,
                          const float* __restrict__ ba2,
                          float* __restrict__ out) {
    __shared__ float s_h[2048];
    __shared__ float s_w[256 * 17];
    __shared__ float s_r[16];
    const int b = blockIdx.x, head = blockIdx.y, tid = threadIdx.x;
    const float* __restrict__ W2 = head ? Wa2 : Wc2;
    const float* __restrict__ b2 = head ? ba2 : bc2;

    {
        const float4* hs = (const float4*)&g_hh[head * 65536 + b * 2048];
        ((float4*)s_h)[tid] = hs[tid];
        ((float4*)s_h)[tid + 256] = hs[tid + 256];
    }
    const int w = tid >> 5, lane = tid & 31;
    float ps[2] = {0.0f, 0.0f};

    // prefetch chunk 0
    float rv[16];
#pragma unroll
    for (int i = 0; i < 16; i++) rv[i] = W2[tid + i * 256];

    for (int c = 0; c < 8; c++) {
        __syncthreads();
#pragma unroll
        for (int i = 0; i < 16; i++) {
            int idx = tid + i * 256;
            s_w[(idx >> 4) * 17 + (idx & 15)] = rv[i];
        }
        __syncthreads();
        if (c < 7) {
#pragma unroll
            for (int i = 0; i < 16; i++)
                rv[i] = W2[(c + 1) * 4096 + tid + i * 256];
        }
#pragma unroll
        for (int dd = 0; dd < 2; dd++) {
            const int f = w + dd * 8;
            float s = 0.0f;
#pragma unroll
            for (int ki = 0; ki < 8; ki++) {
                int k = ki * 32 + lane;
                s = fmaf(s_h[c * 256 + k], s_w[k * 17 + f], s);
            }
            ps[dd] += s;
        }
    }
#pragma unroll
    for (int dd = 0; dd < 2; dd++) {
        float s = ps[dd];
#pragma unroll
        for (int off = 16; off; off >>= 1) s += __shfl_down_sync(0xffffffffu, s, off);
        if (lane == 0) {
            int f = w + dd * 8;
            float v = s + b2[f];
            s_r[f] = LEAKY(v);
        }
    }
    __syncthreads();
    if (head == 0) {
        if (tid == 0) {
            float cr = bc3[0];
#pragma unroll
            for (int f = 0; f < 16; f++) cr = fmaf(s_r[f], Wc3[f], cr);
            out[b] = cr;
        }
    } else {
        if (tid < 16) out[32 + b * 16 + tid] = s_r[tid];
    }
}

// ============================================================
extern "C" void kernel_launch(void* const* d_in, const int* in_sizes, int n_in,
                              void* d_out, int out_size) {
    (void)in_sizes; (void)n_in; (void)out_size;
    const float* inp = (const float*)d_in[0];
    const float* We  = (const float*)d_in[1];
    const float* be  = (const float*)d_in[2];
    const float* Wn  = (const float*)d_in[3];
    const float* bn  = (const float*)d_in[4];
    const float* Wg  = (const float*)d_in[5];
    const float* bgl = (const float*)d_in[6];
    const float* gb  = (const float*)d_in[7];
    const float* Wc1 = (const float*)d_in[8];
    const float* bc1 = (const float*)d_in[9];
    const float* Wc2 = (const float*)d_in[10];
    const float* bc2 = (const float*)d_in[11];
    const float* Wc3 = (const float*)d_in[12];
    const float* bc3 = (const float*)d_in[13];
    const float* Wa1 = (const float*)d_in[14];
    const float* ba1 = (const float*)d_in[15];
    const float* Wa2 = (const float*)d_in[16];
    const float* ba2 = (const float*)d_in[17];

    const int dyn = 128 * 129 * 4;  // 66048 B
    cudaFuncSetAttribute(k1_prep, cudaFuncAttributeMaxDynamicSharedMemorySize, dyn);
    cudaFuncSetAttribute(k2_gcn, cudaFuncAttributeMaxDynamicSharedMemorySize, dyn);

    k1_prep<<<32, 512, dyn>>>(inp, We, be);
    k2_gcn<<<dim3(32, 10), 512, dyn>>>(inp, Wn, bn, Wg, bgl, gb);
    k3_reduce<<<256, 256>>>();
    k4_gemm<<<dim3(16, KSPLIT, 2), 128>>>(Wc1, Wa1);
    k5a_act<<<dim3(64, 2), 256>>>(bc1, ba1);
    k5b_heads<<<dim3(32, 2), 256>>>(Wc2, bc2, Wc3, bc3, Wa2, ba2, (float*)d_out);
}